// round 3
// baseline (speedup 1.0000x reference)
#include <cuda_runtime.h>
#include <math.h>

#define EN   262144
#define NN   65536
#define RTT  8000
#define HH   64
#define BQn  40
#define RRn  200
#define SLOPE 0.22916666666666666f

typedef unsigned long long ull;

// ---------------- device scratch (no allocs allowed) ----------------
__device__ float g_node[NN*HH], g_nacc[NN*HH], g_projA[NN*HH], g_projB[NN*HH];
__device__ float g_rel[RTT*HH], g_racc[RTT*HH], g_pr[RTT*HH], g_pq[RTT*HH];
__device__ float g_finals[3*RTT*HH], g_fin[RTT*HH];
__device__ float g_Ar[RTT], g_Aq[RTT], g_Br[RTT], g_Bq[RTT];
__device__ float g_asum[NN], g_bsum[RTT], g_dinv2[NN];
__device__ float g_aes[EN], g_bes[EN];
__device__ float g_loop[BQn*HH];
__device__ int   g_qrows[BQn];
__device__ int   g_cnt_n[NN], g_off_n[NN+1], g_cur_n[NN];
__device__ int   g_cnt_t[RTT], g_off_t[RTT+1], g_cur_t[RTT];
__device__ int   g_aux[128];
__device__ int4  g_recN[EN];   // (col, et, eq, 0) grouped by row
__device__ int4  g_recT[EN];   // (col, row, eq, 0) grouped by edge_type

__device__ __forceinline__ float actf(float x){ return x >= 0.f ? x : x*SLOPE; }

__device__ __forceinline__ ull pk2(float x, float y){
    ull r; asm("mov.b64 %0, {%1, %2};" : "=l"(r) : "f"(x), "f"(y)); return r;
}
__device__ __forceinline__ void upk2(ull v, float& x, float& y){
    asm("mov.b64 {%0, %1}, %2;" : "=f"(x), "=f"(y) : "l"(v));
}
__device__ __forceinline__ void ffma2(ull& d, ull a, ull b){
    asm("fma.rn.f32x2 %0, %1, %2, %0;" : "+l"(d) : "l"(a), "l"(b));
}

// ---------------- init kernels ----------------
__global__ void k_zero(){
    int i = blockIdx.x*blockDim.x + threadIdx.x;
    if (i < RTT*HH) g_rel[i] = 0.f;
    if (i < NN)     g_cnt_n[i] = 0;
    if (i < RTT)    g_cnt_t[i] = 0;
}

__global__ void k_node_init(const int* __restrict__ labels, const float* __restrict__ pos_emb){
    int idx = blockIdx.x*blockDim.x + threadIdx.x;
    if (idx >= NN*HH) return;
    int n = idx >> 6, h = idx & 63;
    int p = labels[2*n]*4 + labels[2*n+1];
    g_node[idx] = pos_emb[p*HH + h];
}

__global__ void k_set_rows(const int* __restrict__ posns, const float* __restrict__ src){
    int idx = blockIdx.x*blockDim.x + threadIdx.x;
    if (idx >= BQn*HH) return;
    int q = idx >> 6, h = idx & 63;
    g_node[posns[q]*HH + h] = src[h];
}

__global__ void k_rel_init(const int* __restrict__ qrel, const float* __restrict__ srel,
                           const float* __restrict__ lemb){
    int idx = blockIdx.x*blockDim.x + threadIdx.x;
    if (idx >= BQn*HH) return;
    int q = idx >> 6, h = idx & 63;
    int qrow = qrel[q] + q*RRn;
    if (h == 0) g_qrows[q] = qrow;
    g_rel[qrow*HH + h] = srel[h];
    g_loop[idx] = lemb[h];
}

// ---------------- CSR build ----------------
__global__ void k_hist(const int* __restrict__ row, const int* __restrict__ et){
    int e = blockIdx.x*blockDim.x + threadIdx.x;
    if (e >= EN) return;
    atomicAdd(&g_cnt_n[row[e]], 1);
    atomicAdd(&g_cnt_t[et[e]], 1);
}

__device__ __forceinline__ void scan1_body(const int* cnt, int* off, int* aux, int n, int blk){
    __shared__ int sh[1024];
    int t = threadIdx.x, i = blk*1024 + t;
    int v = (i < n) ? cnt[i] : 0;
    sh[t] = v; __syncthreads();
    for (int d = 1; d < 1024; d <<= 1){
        int u = (t >= d) ? sh[t-d] : 0;
        __syncthreads();
        sh[t] += u;
        __syncthreads();
    }
    if (i < n) off[i] = sh[t] - v;
    if (t == 1023) aux[blk] = sh[t];
}

__global__ void k_scan1(){
    if (blockIdx.x < 64) scan1_body(g_cnt_n, g_off_n, g_aux, NN, blockIdx.x);
    else                 scan1_body(g_cnt_t, g_off_t, g_aux + 64, RTT, blockIdx.x - 64);
}

__global__ void k_scan2(){
    __shared__ int sh[64];
    int t = threadIdx.x;
    int* aux = blockIdx.x ? (g_aux + 64) : g_aux;
    int m = blockIdx.x ? 8 : 64;
    int v = (t < m) ? aux[t] : 0;
    sh[t] = v; __syncthreads();
    for (int d = 1; d < 64; d <<= 1){
        int u = (t >= d) ? sh[t-d] : 0;
        __syncthreads();
        sh[t] += u;
        __syncthreads();
    }
    if (t < m) aux[t] = sh[t] - v;  // exclusive
}

__global__ void k_scan3(){
    int t = threadIdx.x;
    if (blockIdx.x < 64){
        int i = blockIdx.x*1024 + t;
        int o = g_off_n[i] + g_aux[blockIdx.x];
        g_off_n[i] = o; g_cur_n[i] = o;
        if (i == 0) g_off_n[NN] = EN;
    } else {
        int b2 = blockIdx.x - 64;
        int i = b2*1024 + t;
        if (i < RTT){
            int o = g_off_t[i] + g_aux[64 + b2];
            g_off_t[i] = o; g_cur_t[i] = o;
        }
        if (i == 0) g_off_t[RTT] = EN;
    }
}

__global__ void k_scatter(const int* __restrict__ col, const int* __restrict__ row,
                          const int* __restrict__ et, const int* __restrict__ eq){
    int e = blockIdx.x*blockDim.x + threadIdx.x;
    if (e >= EN) return;
    int c = col[e], r = row[e], t = et[e], q = eq[e];
    int p  = atomicAdd(&g_cur_n[r], 1);
    g_recN[p] = make_int4(c, t, q, 0);
    int p2 = atomicAdd(&g_cur_t[t], 1);
    g_recT[p2] = make_int4(c, r, q, 0);
}

__global__ void k_dinv2(){
    int n = blockIdx.x*blockDim.x + threadIdx.x;
    if (n >= NN) return;
    int d = g_off_n[n+1] - g_off_n[n];
    g_dinv2[n] = d > 0 ? 1.f/(float)d : 0.f;
}

// ---------------- core proj body: 64-row tile, duplicated-weight smem ----------------
// out[M,64] = in[M,64*nchunk selected cols] @ W[:, co:co+64]^T   per slice
// TWO: two output slices (co1->out1, co2->out2). DOLN: LN(act(x+bias)(+resid)) epilogue.
template<int TWO, int DOLN>
__device__ __forceinline__ void proj_body(
        int blk, const float* __restrict__ in, int nchunk, size_t cstride,
        const float* __restrict__ W, int wstride, int co1, int co2,
        float* __restrict__ out1, float* __restrict__ out2,
        const float* __restrict__ bias, const float* __restrict__ resid,
        float* __restrict__ outB)
{
    __shared__ float In[64][68];
    __shared__ float WtD[32][132];
    const int t = threadIdx.x;
    const int op = t & 31, rg = t >> 5;
    const size_t rowbase = (size_t)blk * 64;

    for (int s = 0; s <= TWO; s++){
        int co = (s == 0) ? co1 : co2;
        ull A[4], B[4];
        ull z = pk2(0.f, 0.f);
        #pragma unroll
        for (int j=0;j<4;j++){ A[j]=z; B[j]=z; }
        for (int c = 0; c < nchunk; c++){
            #pragma unroll 1
            for (int h = 0; h < 2; h++){
                __syncthreads();
                if (h == 0 && s == 0){
                    const float4* in4 = (const float4*)(in + (size_t)c*cstride + rowbase*HH);
                    for (int idx = t; idx < 1024; idx += 256){
                        int r = idx >> 4, kq = idx & 15;
                        float4 v = in4[idx];
                        In[4*kq+0][r]=v.x; In[4*kq+1][r]=v.y;
                        In[4*kq+2][r]=v.z; In[4*kq+3][r]=v.w;
                    }
                }
                int cob = co + c*64 + h*32;
                for (int idx = t; idx < 2048; idx += 256){
                    int o = idx >> 5, k = idx & 31;
                    float w = W[o*wstride + cob + k];
                    *(float2*)&WtD[k][2*o] = make_float2(w, w);
                }
                __syncthreads();
                #pragma unroll 8
                for (int k = 0; k < 32; k++){
                    ulonglong2 wv  = *(const ulonglong2*)&WtD[k][4*op];
                    ulonglong2 v01 = *(const ulonglong2*)&In[h*32+k][rg*8];
                    ulonglong2 v23 = *(const ulonglong2*)&In[h*32+k][rg*8+4];
                    ffma2(A[0], v01.x, wv.x); ffma2(A[1], v01.y, wv.x);
                    ffma2(A[2], v23.x, wv.x); ffma2(A[3], v23.y, wv.x);
                    ffma2(B[0], v01.x, wv.y); ffma2(B[1], v01.y, wv.y);
                    ffma2(B[2], v23.x, wv.y); ffma2(B[3], v23.y, wv.y);
                }
            }
        }
        float* o1 = (s == 0) ? out1 : out2;
        if (!DOLN){
            #pragma unroll
            for (int j = 0; j < 4; j++){
                size_t r0 = rowbase + rg*8 + 2*j;
                float a0,a1,b0,b1;
                upk2(A[j], a0, a1); upk2(B[j], b0, b1);
                *(float2*)(o1 + r0*HH + 2*op)     = make_float2(a0, b0);
                *(float2*)(o1 + (r0+1)*HH + 2*op) = make_float2(a1, b1);
            }
        } else {
            float2 bv = *(const float2*)(bias + 2*op);
            #pragma unroll
            for (int j = 0; j < 4; j++){
                size_t r0 = rowbase + rg*8 + 2*j;
                float a0,a1,b0,b1;
                upk2(A[j], a0, a1); upk2(B[j], b0, b1);
                float y00 = actf(a0 + bv.x), y01 = actf(b0 + bv.y);
                float y10 = actf(a1 + bv.x), y11 = actf(b1 + bv.y);
                if (resid){
                    float2 rv0 = *(const float2*)(resid + r0*HH + 2*op);
                    float2 rv1 = *(const float2*)(resid + (r0+1)*HH + 2*op);
                    y00 += rv0.x; y01 += rv0.y; y10 += rv1.x; y11 += rv1.y;
                }
                float s0 = y00+y01, q0 = y00*y00+y01*y01;
                float s1 = y10+y11, q1 = y10*y10+y11*y11;
                #pragma unroll
                for (int o=16;o;o>>=1){
                    s0 += __shfl_xor_sync(0xffffffffu,s0,o);
                    q0 += __shfl_xor_sync(0xffffffffu,q0,o);
                    s1 += __shfl_xor_sync(0xffffffffu,s1,o);
                    q1 += __shfl_xor_sync(0xffffffffu,q1,o);
                }
                float m0 = s0*(1.f/64.f), m1 = s1*(1.f/64.f);
                float i0 = rsqrtf(q0*(1.f/64.f) - m0*m0 + 1e-5f);
                float i1 = rsqrtf(q1*(1.f/64.f) - m1*m1 + 1e-5f);
                float2 w0 = make_float2((y00-m0)*i0, (y01-m0)*i0);
                float2 w1 = make_float2((y10-m1)*i1, (y11-m1)*i1);
                *(float2*)(o1 + r0*HH + 2*op)     = w0;
                *(float2*)(o1 + (r0+1)*HH + 2*op) = w1;
                if (outB){
                    *(float2*)(outB + r0*HH + 2*op)     = w0;
                    *(float2*)(outB + (r0+1)*HH + 2*op) = w1;
                }
            }
        }
    }
}

// ---------------- per-relation attention scalars ----------------
__device__ __forceinline__ void relscal_body(int b2, const float* __restrict__ Wa,
        const float* __restrict__ Wb, const float* __restrict__ ba, const float* __restrict__ bb){
    int w = b2*8 + (threadIdx.x >> 5);
    int lane = threadIdx.x & 31;
    if (w >= RTT) return;
    float2 v = *(const float2*)(g_rel + (size_t)w*HH + 2*lane);
    float a0 = actf(v.x), a1 = actf(v.y);
    float2 wa1 = *(const float2*)(Wa + 2*lane);
    float2 wa2 = *(const float2*)(Wa + 64 + 2*lane);
    float2 wb1 = *(const float2*)(Wb + 2*lane);
    float2 wb2 = *(const float2*)(Wb + 64 + 2*lane);
    float sar = a0*wa1.x + a1*wa1.y;
    float saq = a0*wa2.x + a1*wa2.y;
    float sbr = v.x*wb1.x + v.y*wb1.y;
    float sbq = v.x*wb2.x + v.y*wb2.y;
    #pragma unroll
    for (int o=16;o;o>>=1){
        sar += __shfl_xor_sync(0xffffffffu,sar,o);
        saq += __shfl_xor_sync(0xffffffffu,saq,o);
        sbr += __shfl_xor_sync(0xffffffffu,sbr,o);
        sbq += __shfl_xor_sync(0xffffffffu,sbq,o);
    }
    if (lane == 0){ g_Ar[w]=sar+ba[0]; g_Aq[w]=saq; g_Br[w]=sbr+bb[0]; g_Bq[w]=sbq; }
}

// ---------------- stage kernels ----------------
// stage1: Pr+Pq (rel, TWO) | Ph (node) | relscal
__global__ __launch_bounds__(256, 3) void k_stage1(const float* __restrict__ Wmsg,
        const float* __restrict__ Wa, const float* __restrict__ Wb,
        const float* __restrict__ ba, const float* __restrict__ bb){
    int b = blockIdx.x;
    if (b < 125)
        proj_body<1,0>(b, g_rel, 1, 0, Wmsg, 192, 64, 128, g_pr, g_pq, 0, 0, 0);
    else if (b < 1149)
        proj_body<0,0>(b-125, g_node, 1, 0, Wmsg, 192, 0, 0, g_projA, 0, 0, 0, 0);
    else
        relscal_body(b-1149, Wa, Wb, ba, bb);
}

// stage4: Ph2+Pt2 (node, TWO) | Pq2 (rel)
__global__ __launch_bounds__(256, 3) void k_stage4(const float* __restrict__ Wht){
    int b = blockIdx.x;
    if (b < 1024)
        proj_body<1,0>(b, g_node, 1, 0, Wht, 192, 0, 64, g_projA, g_projB, 0, 0, 0);
    else
        proj_body<0,0>(b-1024, g_rel, 1, 0, Wht, 192, 128, 0, g_pq, 0, 0, 0, 0);
}

// stage3: node = LN(act(nacc @ We^T + be))
__global__ __launch_bounds__(256, 3) void k_stage3(const float* __restrict__ We,
        const float* __restrict__ be){
    proj_body<0,1>(blockIdx.x, g_nacc, 1, 0, We, 64, 0, 0, g_node, 0, be, 0, 0);
}

// stage6: rel = LN(act(racc @ Wr^T + br) + rel); finals[i] = rel
__global__ __launch_bounds__(256, 3) void k_stage6(const float* __restrict__ Wr,
        const float* __restrict__ br, float* __restrict__ finals_i){
    proj_body<0,1>(blockIdx.x, g_racc, 1, 0, Wr, 64, 0, 0, g_rel, 0, br, g_rel, finals_i);
}

// final: fin = LN(act(concat(finals) @ Wf^T + bf))   (K=192 via 3 chunks)
__global__ __launch_bounds__(256, 3) void k_final(const float* __restrict__ Wf,
        const float* __restrict__ bf){
    proj_body<0,1>(blockIdx.x, g_finals, 3, (size_t)RTT*HH, Wf, 192, 0, 0, g_fin, 0, bf, 0, 0);
}

// ---------------- fused attention segment sums ----------------
__global__ void k_absum(){
    if (blockIdx.x < 256){
        int n = blockIdx.x*256 + threadIdx.x;
        int b = g_off_n[n], e = g_off_n[n+1];
        float s = 0.f;
        for (int j = b; j < e; j++){
            int4 rc = g_recN[j];
            float a = __expf(g_Ar[rc.y] + g_Aq[rc.z]);
            g_aes[j] = a; s += a;
        }
        g_asum[n] = s;
    } else {
        int w = (blockIdx.x - 256)*8 + (threadIdx.x >> 5);
        int lane = threadIdx.x & 31;
        if (w >= RTT) return;
        int b = g_off_t[w], e = g_off_t[w+1];
        float br = g_Br[w];
        float s = 0.f;
        for (int j = b + lane; j < e; j += 32){
            int4 rc = g_recT[j];
            float bv = __expf(br + g_Bq[rc.z]);
            g_bes[j] = bv; s += bv;
        }
        #pragma unroll
        for (int o=16;o;o>>=1) s += __shfl_xor_sync(0xffffffffu,s,o);
        if (lane == 0) g_bsum[w] = s;
    }
}

// ---------------- edge message aggregation: warp per node (CSR) ----------------
__global__ void k_msg_agg(const int* __restrict__ row, const float* __restrict__ bmsg){
    int w = (blockIdx.x*blockDim.x + threadIdx.x) >> 5;
    int lane = threadIdx.x & 31;
    if (w >= NN) return;
    int b = g_off_n[w], e = g_off_n[w+1];
    float denom = g_asum[row[w]] + 1e-10f;    // faithful a_sum[row[row_e]]
    float sc0 = g_dinv2[w] / denom;
    float2 bm = *(const float2*)(bmsg + 2*lane);
    float ax = 0.f, ay = 0.f;
    for (int j = b; j < e; j++){
        int4 rc = g_recN[j];
        float coef = g_aes[j] * sc0 * g_dinv2[rc.x];
        float2 ph = *(const float2*)(g_projA + (size_t)rc.x*HH + 2*lane);
        float2 pr = *(const float2*)(g_pr    + (size_t)rc.y*HH + 2*lane);
        float2 pq = *(const float2*)(g_pq    + (size_t)rc.z*HH + 2*lane);
        ax += coef*actf(ph.x + pr.x + pq.x + bm.x);
        ay += coef*actf(ph.y + pr.y + pq.y + bm.y);
    }
    *(float2*)(g_nacc + (size_t)w*HH + 2*lane) = make_float2(ax, ay);
}

// ---------------- ht2r aggregation: warp per relation type (CSR) ----------------
__global__ void k_ht2r_agg(const int* __restrict__ et, const float* __restrict__ bht){
    int w = (blockIdx.x*blockDim.x + threadIdx.x) >> 5;
    int lane = threadIdx.x & 31;
    if (w >= RTT) return;
    int b = g_off_t[w], e = g_off_t[w+1];
    float inv_denom = 1.f / (g_bsum[et[w]] + 1e-10f);  // faithful b_sum[et[et_e]]
    float2 bm = *(const float2*)(bht + 2*lane);
    float ax = 0.f, ay = 0.f;
    for (int j = b; j < e; j++){
        int4 rc = g_recT[j];
        float coef = g_bes[j] * inv_denom;
        float2 ph = *(const float2*)(g_projA + (size_t)rc.x*HH + 2*lane);
        float2 pt = *(const float2*)(g_projB + (size_t)rc.y*HH + 2*lane);
        float2 pq = *(const float2*)(g_pq    + (size_t)rc.z*HH + 2*lane);
        ax += coef*actf(ph.x + pt.x + pq.x + bm.x);
        ay += coef*actf(ph.y + pt.y + pq.y + bm.y);
    }
    *(float2*)(g_racc + (size_t)w*HH + 2*lane) = make_float2(ax, ay);
}

// ---------------- loop update (40 rows) ----------------
__global__ void k_loop(const float* __restrict__ Wl, const float* __restrict__ bl){
    __shared__ float cat[128];
    __shared__ float ps[2], pq2[2];
    int q = blockIdx.x, t = threadIdx.x;   // 64 threads
    int qrow = g_qrows[q];
    float lv = g_loop[q*HH + t];
    cat[t] = lv;
    cat[64+t] = g_rel[qrow*HH + t];
    __syncthreads();
    float s = bl[t];
    #pragma unroll 8
    for (int k=0;k<128;k++) s = fmaf(cat[k], Wl[t*128+k], s);
    float y = lv + actf(s);
    float ss = y, sq = y*y;
    #pragma unroll
    for (int o=16;o;o>>=1){ ss += __shfl_xor_sync(0xffffffffu,ss,o); sq += __shfl_xor_sync(0xffffffffu,sq,o); }
    if ((t&31)==0){ ps[t>>5]=ss; pq2[t>>5]=sq; }
    __syncthreads();
    float S = ps[0]+ps[1], Q = pq2[0]+pq2[1];
    float m = S*(1.f/64.f);
    float var = Q*(1.f/64.f) - m*m;
    float inv = rsqrtf(var + 1e-5f);
    g_loop[q*HH + t] = (y-m)*inv;
}

// ---------------- output means ----------------
__global__ void k_mean(float* __restrict__ out){
    int idx = blockIdx.x*blockDim.x + threadIdx.x;
    if (idx >= 8*201*64) return;
    int h = idx & 63;
    int rb = idx >> 6;
    int r = rb % 201;
    int b = rb / 201;
    float s = 0.f;
    if (r < 200){
        #pragma unroll
        for (int s5=0;s5<5;s5++) s += g_fin[(b*1000 + s5*200 + r)*HH + h];
    } else {
        #pragma unroll
        for (int s5=0;s5<5;s5++) s += g_loop[(b*5 + s5)*HH + h];
    }
    out[idx] = s * 0.2f;
}

// ---------------- host ----------------
struct Ptrs {
    const int *ei,*et,*eq,*hp,*tp,*qr,*lab;
    const float *pos,*srel,*lemb,*Wmsg,*bmsg,*Wht,*bht,*Wa,*ba,*Wb,*bb,*Wl,*bl,*We,*be,*Wr,*br,*Wf,*bf;
};

static void resolve(void* const* d, const int* sz, int n, Ptrs& p){
    int gi, wi;
    if (sz[0] == 2*EN){
        gi = 0;
        wi = (n > 10 && sz[7] == 1 && sz[8] == 1 && sz[9] == 1) ? 10 : 7;
    } else {
        wi = 0; gi = 19;
    }
    p.ei  = (const int*)d[gi+0]; p.et = (const int*)d[gi+1]; p.eq = (const int*)d[gi+2];
    p.hp  = (const int*)d[gi+3]; p.tp = (const int*)d[gi+4]; p.qr = (const int*)d[gi+5];
    p.lab = (const int*)d[gi+6];
    p.pos  = (const float*)d[wi+0];  p.srel = (const float*)d[wi+1];  p.lemb = (const float*)d[wi+2];
    p.Wmsg = (const float*)d[wi+3];  p.bmsg = (const float*)d[wi+4];
    p.Wht  = (const float*)d[wi+5];  p.bht  = (const float*)d[wi+6];
    p.Wa   = (const float*)d[wi+7];  p.ba   = (const float*)d[wi+8];
    p.Wb   = (const float*)d[wi+9];  p.bb   = (const float*)d[wi+10];
    p.Wl   = (const float*)d[wi+11]; p.bl   = (const float*)d[wi+12];
    p.We   = (const float*)d[wi+13]; p.be   = (const float*)d[wi+14];
    p.Wr   = (const float*)d[wi+15]; p.br   = (const float*)d[wi+16];
    p.Wf   = (const float*)d[wi+17]; p.bf   = (const float*)d[wi+18];
}

extern "C" void kernel_launch(void* const* d_in, const int* in_sizes, int n_in,
                              void* d_out, int out_size){
    Ptrs p; resolve(d_in, in_sizes, n_in, p);
    const int* col = p.ei;
    const int* row = p.ei + EN;

    float* s_finals;
    cudaGetSymbolAddress((void**)&s_finals, g_finals);

    // ---- init + CSR build ----
    k_zero<<<RTT*HH/256,256>>>();
    k_node_init<<<NN*HH/256,256>>>(p.lab, p.pos);
    k_set_rows<<<(BQn*HH+255)/256,256>>>(p.hp, p.pos + 0*HH);
    k_set_rows<<<(BQn*HH+255)/256,256>>>(p.tp, p.pos + 1*HH);
    k_rel_init<<<(BQn*HH+255)/256,256>>>(p.qr, p.srel, p.lemb);
    k_hist<<<EN/256,256>>>(row, p.et);
    k_scan1<<<72,1024>>>();
    k_scan2<<<2,64>>>();
    k_scan3<<<72,1024>>>();
    k_scatter<<<EN/256,256>>>(col, row, p.et, p.eq);
    k_dinv2<<<NN/256,256>>>();

    for (int i = 0; i < 3; i++){
        const float* Wmsg = p.Wmsg + i*HH*192;
        const float* bmsg = p.bmsg + i*HH;
        const float* Wht  = p.Wht  + i*HH*192;
        const float* bht  = p.bht  + i*HH;

        k_stage1<<<2149,256>>>(Wmsg, p.Wa + i*128, p.Wb + i*128, p.ba + i, p.bb + i);
        k_absum<<<1256,256>>>();
        k_msg_agg<<<NN*32/256,256>>>(row, bmsg);
        k_stage3<<<1024,256>>>(p.We + i*HH*HH, p.be + i*HH);
        k_stage4<<<1149,256>>>(Wht);
        k_ht2r_agg<<<RTT*32/256,256>>>(p.et, bht);
        k_stage6<<<125,256>>>(p.Wr + i*HH*HH, p.br + i*HH, s_finals + i*RTT*HH);
        k_loop<<<BQn,64>>>(p.Wl + i*HH*128, p.bl + i*HH);
    }

    k_final<<<125,256>>>(p.Wf, p.bf);
    k_mean<<<(8*201*64+255)/256,256>>>((float*)d_out);
}

// round 4
// speedup vs baseline: 1.1116x; 1.1116x over previous
#include <cuda_runtime.h>
#include <math.h>

#define EN   262144
#define NN   65536
#define RTT  8000
#define HH   64
#define BQn  40
#define RRn  200
#define SLOPE 0.22916666666666666f

typedef unsigned long long ull;

// ---------------- device scratch (no allocs allowed) ----------------
__device__ float g_node[NN*HH], g_nacc[NN*HH], g_projA[NN*HH], g_projB[NN*HH];
__device__ float g_rel[RTT*HH], g_racc[RTT*HH], g_pr[RTT*HH], g_pq[RTT*HH];
__device__ float g_finals[3*RTT*HH], g_fin[RTT*HH];
__device__ float g_Ar[RTT], g_Aq[RTT], g_Br[RTT], g_Bq[RTT];
__device__ float g_asum[NN], g_bsum[RTT], g_dinv2[NN];
__device__ float g_aes[EN], g_bes[EN];
__device__ float g_loop[BQn*HH];
__device__ int   g_qrows[BQn];
__device__ int   g_cnt_n[NN], g_off_n[NN+1], g_cur_n[NN];
__device__ int   g_cnt_t[RTT], g_off_t[RTT+1], g_cur_t[RTT];
__device__ int   g_aux[128];
__device__ int4  g_recN[EN];   // (col, et, eq, 0) grouped by row
__device__ int4  g_recT[EN];   // (col, row, eq, 0) grouped by edge_type

__device__ __forceinline__ float actf(float x){ return x >= 0.f ? x : x*SLOPE; }

__device__ __forceinline__ ull pk2(float x, float y){
    ull r; asm("mov.b64 %0, {%1, %2};" : "=l"(r) : "f"(x), "f"(y)); return r;
}
__device__ __forceinline__ void upk2(ull v, float& x, float& y){
    asm("mov.b64 {%0, %1}, %2;" : "=f"(x), "=f"(y) : "l"(v));
}
__device__ __forceinline__ void ffma2(ull& d, ull a, ull b){
    asm("fma.rn.f32x2 %0, %1, %2, %0;" : "+l"(d) : "l"(a), "l"(b));
}

// ---------------- init kernels ----------------
__global__ void k_zero(){
    int i = blockIdx.x*blockDim.x + threadIdx.x;
    if (i < RTT*HH) g_rel[i] = 0.f;
    if (i < NN)     g_cnt_n[i] = 0;
    if (i < RTT)    g_cnt_t[i] = 0;
}

__global__ void k_node_init(const int* __restrict__ labels, const float* __restrict__ pos_emb){
    int idx = blockIdx.x*blockDim.x + threadIdx.x;
    if (idx >= NN*HH) return;
    int n = idx >> 6, h = idx & 63;
    int p = labels[2*n]*4 + labels[2*n+1];
    g_node[idx] = pos_emb[p*HH + h];
}

__global__ void k_set_rows(const int* __restrict__ posns, const float* __restrict__ src){
    int idx = blockIdx.x*blockDim.x + threadIdx.x;
    if (idx >= BQn*HH) return;
    int q = idx >> 6, h = idx & 63;
    g_node[posns[q]*HH + h] = src[h];
}

__global__ void k_rel_init(const int* __restrict__ qrel, const float* __restrict__ srel,
                           const float* __restrict__ lemb){
    int idx = blockIdx.x*blockDim.x + threadIdx.x;
    if (idx >= BQn*HH) return;
    int q = idx >> 6, h = idx & 63;
    int qrow = qrel[q] + q*RRn;
    if (h == 0) g_qrows[q] = qrow;
    g_rel[qrow*HH + h] = srel[h];
    g_loop[idx] = lemb[h];
}

// ---------------- CSR build ----------------
__global__ void k_hist(const int* __restrict__ row, const int* __restrict__ et){
    int e = blockIdx.x*blockDim.x + threadIdx.x;
    if (e >= EN) return;
    atomicAdd(&g_cnt_n[row[e]], 1);
    atomicAdd(&g_cnt_t[et[e]], 1);
}

__device__ __forceinline__ void scan1_body(const int* cnt, int* off, int* aux, int n, int blk){
    __shared__ int sh[1024];
    int t = threadIdx.x, i = blk*1024 + t;
    int v = (i < n) ? cnt[i] : 0;
    sh[t] = v; __syncthreads();
    for (int d = 1; d < 1024; d <<= 1){
        int u = (t >= d) ? sh[t-d] : 0;
        __syncthreads();
        sh[t] += u;
        __syncthreads();
    }
    if (i < n) off[i] = sh[t] - v;
    if (t == 1023) aux[blk] = sh[t];
}

__global__ void k_scan1(){
    if (blockIdx.x < 64) scan1_body(g_cnt_n, g_off_n, g_aux, NN, blockIdx.x);
    else                 scan1_body(g_cnt_t, g_off_t, g_aux + 64, RTT, blockIdx.x - 64);
}

__global__ void k_scan2(){
    __shared__ int sh[64];
    int t = threadIdx.x;
    int* aux = blockIdx.x ? (g_aux + 64) : g_aux;
    int m = blockIdx.x ? 8 : 64;
    int v = (t < m) ? aux[t] : 0;
    sh[t] = v; __syncthreads();
    for (int d = 1; d < 64; d <<= 1){
        int u = (t >= d) ? sh[t-d] : 0;
        __syncthreads();
        sh[t] += u;
        __syncthreads();
    }
    if (t < m) aux[t] = sh[t] - v;  // exclusive
}

__global__ void k_scan3(){
    int t = threadIdx.x;
    if (blockIdx.x < 64){
        int i = blockIdx.x*1024 + t;
        int o = g_off_n[i] + g_aux[blockIdx.x];
        g_off_n[i] = o; g_cur_n[i] = o;
        if (i == 0) g_off_n[NN] = EN;
    } else {
        int b2 = blockIdx.x - 64;
        int i = b2*1024 + t;
        if (i < RTT){
            int o = g_off_t[i] + g_aux[64 + b2];
            g_off_t[i] = o; g_cur_t[i] = o;
        }
        if (i == 0) g_off_t[RTT] = EN;
    }
}

__global__ void k_scatter(const int* __restrict__ col, const int* __restrict__ row,
                          const int* __restrict__ et, const int* __restrict__ eq){
    int e = blockIdx.x*blockDim.x + threadIdx.x;
    if (e >= EN) return;
    int c = col[e], r = row[e], t = et[e], q = eq[e];
    int p  = atomicAdd(&g_cur_n[r], 1);
    g_recN[p] = make_int4(c, t, q, 0);
    int p2 = atomicAdd(&g_cur_t[t], 1);
    g_recT[p2] = make_int4(c, r, q, 0);
}

__global__ void k_dinv2(){
    int n = blockIdx.x*blockDim.x + threadIdx.x;
    if (n >= NN) return;
    int d = g_off_n[n+1] - g_off_n[n];
    g_dinv2[n] = d > 0 ? 1.f/(float)d : 0.f;
}

// ---------------- core proj body v4: conflict-free smem, dual-slice shared v ----------------
// out[M,64] = in[M, 64*nchunk] @ W[:, co:co+64]^T per slice.
// Thread layout: lane op -> outputs (2op, 2op+1); warp rg -> rows rg*8..rg*8+7 (4 FFMA2 pairs).
// In[k][r] transposed with r-fast conflict-free fill; Wt non-duplicated, LDS.64 reads.
template<int TWO, int DOLN>
__device__ __forceinline__ void proj_body(
        int blk, const float* __restrict__ in, int nchunk, size_t cstride,
        const float* __restrict__ W, int wstride, int co1, int co2,
        float* __restrict__ out1, float* __restrict__ out2,
        const float* __restrict__ bias, const float* __restrict__ resid,
        float* __restrict__ outB)
{
    __shared__ float In[64][68];
    __shared__ float Wt[TWO+1][32][66];
    const int t = threadIdx.x;
    const int op = t & 31, rg = t >> 5;
    const size_t rowbase = (size_t)blk * 64;

    ull A0[4], B0[4], A1[4], B1[4];
    {
        ull z = pk2(0.f, 0.f);
        #pragma unroll
        for (int j=0;j<4;j++){ A0[j]=z; B0[j]=z; A1[j]=z; B1[j]=z; }
    }

    for (int c = 0; c < nchunk; c++){
        #pragma unroll 1
        for (int h = 0; h < 2; h++){
            __syncthreads();
            if (h == 0){
                // r-fast fill: lanes vary r -> STS conflict-free (any stride)
                const float* inc = in + (size_t)c*cstride + rowbase*HH;
                for (int idx = t; idx < 1024; idx += 256){
                    int r = idx & 63, kq = idx >> 6;
                    float4 v = *(const float4*)(inc + (size_t)r*HH + 4*kq);
                    In[4*kq+0][r]=v.x; In[4*kq+1][r]=v.y;
                    In[4*kq+2][r]=v.z; In[4*kq+3][r]=v.w;
                }
            }
            // weight tiles: gmem coalesced (lanes vary k); STS 2-way max
            {
                int cob = c*64 + h*32;
                for (int idx = t; idx < 2048; idx += 256){
                    int o = idx >> 5, k = idx & 31;
                    Wt[0][k][o] = W[o*wstride + co1 + cob + k];
                    if (TWO) Wt[TWO][k][o] = W[o*wstride + co2 + cob + k];
                }
            }
            __syncthreads();
            #pragma unroll 8
            for (int k = 0; k < 32; k++){
                ulonglong2 v01 = *(const ulonglong2*)&In[h*32+k][rg*8];     // broadcast
                ulonglong2 v23 = *(const ulonglong2*)&In[h*32+k][rg*8+4];   // broadcast
                float2 w0 = *(const float2*)&Wt[0][k][2*op];                // lane-consecutive LDS.64
                ull wa = pk2(w0.x, w0.x), wb = pk2(w0.y, w0.y);
                ffma2(A0[0], v01.x, wa); ffma2(A0[1], v01.y, wa);
                ffma2(A0[2], v23.x, wa); ffma2(A0[3], v23.y, wa);
                ffma2(B0[0], v01.x, wb); ffma2(B0[1], v01.y, wb);
                ffma2(B0[2], v23.x, wb); ffma2(B0[3], v23.y, wb);
                if (TWO){
                    float2 w1 = *(const float2*)&Wt[TWO][k][2*op];
                    ull wc = pk2(w1.x, w1.x), wd = pk2(w1.y, w1.y);
                    ffma2(A1[0], v01.x, wc); ffma2(A1[1], v01.y, wc);
                    ffma2(A1[2], v23.x, wc); ffma2(A1[3], v23.y, wc);
                    ffma2(B1[0], v01.x, wd); ffma2(B1[1], v01.y, wd);
                    ffma2(B1[2], v23.x, wd); ffma2(B1[3], v23.y, wd);
                }
            }
        }
    }

    if (!DOLN){
        #pragma unroll
        for (int j = 0; j < 4; j++){
            size_t r0 = rowbase + rg*8 + 2*j;
            float a0,a1,b0,b1;
            upk2(A0[j], a0, a1); upk2(B0[j], b0, b1);
            *(float2*)(out1 + r0*HH + 2*op)     = make_float2(a0, b0);
            *(float2*)(out1 + (r0+1)*HH + 2*op) = make_float2(a1, b1);
            if (TWO){
                upk2(A1[j], a0, a1); upk2(B1[j], b0, b1);
                *(float2*)(out2 + r0*HH + 2*op)     = make_float2(a0, b0);
                *(float2*)(out2 + (r0+1)*HH + 2*op) = make_float2(a1, b1);
            }
        }
    } else {
        float2 bv = *(const float2*)(bias + 2*op);
        #pragma unroll
        for (int j = 0; j < 4; j++){
            size_t r0 = rowbase + rg*8 + 2*j;
            float a0,a1,b0,b1;
            upk2(A0[j], a0, a1); upk2(B0[j], b0, b1);
            float y00 = actf(a0 + bv.x), y01 = actf(b0 + bv.y);
            float y10 = actf(a1 + bv.x), y11 = actf(b1 + bv.y);
            if (resid){
                float2 rv0 = *(const float2*)(resid + r0*HH + 2*op);
                float2 rv1 = *(const float2*)(resid + (r0+1)*HH + 2*op);
                y00 += rv0.x; y01 += rv0.y; y10 += rv1.x; y11 += rv1.y;
            }
            float s0 = y00+y01, q0 = y00*y00+y01*y01;
            float s1 = y10+y11, q1 = y10*y10+y11*y11;
            #pragma unroll
            for (int o=16;o;o>>=1){
                s0 += __shfl_xor_sync(0xffffffffu,s0,o);
                q0 += __shfl_xor_sync(0xffffffffu,q0,o);
                s1 += __shfl_xor_sync(0xffffffffu,s1,o);
                q1 += __shfl_xor_sync(0xffffffffu,q1,o);
            }
            float m0 = s0*(1.f/64.f), m1 = s1*(1.f/64.f);
            float i0 = rsqrtf(q0*(1.f/64.f) - m0*m0 + 1e-5f);
            float i1 = rsqrtf(q1*(1.f/64.f) - m1*m1 + 1e-5f);
            float2 w0 = make_float2((y00-m0)*i0, (y01-m0)*i0);
            float2 w1 = make_float2((y10-m1)*i1, (y11-m1)*i1);
            *(float2*)(out1 + r0*HH + 2*op)     = w0;
            *(float2*)(out1 + (r0+1)*HH + 2*op) = w1;
            if (outB){
                *(float2*)(outB + r0*HH + 2*op)     = w0;
                *(float2*)(outB + (r0+1)*HH + 2*op) = w1;
            }
        }
    }
}

// ---------------- per-relation attention scalars ----------------
__device__ __forceinline__ void relscal_body(int b2, const float* __restrict__ Wa,
        const float* __restrict__ Wb, const float* __restrict__ ba, const float* __restrict__ bb){
    int w = b2*8 + (threadIdx.x >> 5);
    int lane = threadIdx.x & 31;
    if (w >= RTT) return;
    float2 v = *(const float2*)(g_rel + (size_t)w*HH + 2*lane);
    float a0 = actf(v.x), a1 = actf(v.y);
    float2 wa1 = *(const float2*)(Wa + 2*lane);
    float2 wa2 = *(const float2*)(Wa + 64 + 2*lane);
    float2 wb1 = *(const float2*)(Wb + 2*lane);
    float2 wb2 = *(const float2*)(Wb + 64 + 2*lane);
    float sar = a0*wa1.x + a1*wa1.y;
    float saq = a0*wa2.x + a1*wa2.y;
    float sbr = v.x*wb1.x + v.y*wb1.y;
    float sbq = v.x*wb2.x + v.y*wb2.y;
    #pragma unroll
    for (int o=16;o;o>>=1){
        sar += __shfl_xor_sync(0xffffffffu,sar,o);
        saq += __shfl_xor_sync(0xffffffffu,saq,o);
        sbr += __shfl_xor_sync(0xffffffffu,sbr,o);
        sbq += __shfl_xor_sync(0xffffffffu,sbq,o);
    }
    if (lane == 0){ g_Ar[w]=sar+ba[0]; g_Aq[w]=saq; g_Br[w]=sbr+bb[0]; g_Bq[w]=sbq; }
}

// ---------------- stage kernels ----------------
// stage1: Pr+Pq (rel, TWO) | Ph (node) | relscal
__global__ __launch_bounds__(256, 3) void k_stage1(const float* __restrict__ Wmsg,
        const float* __restrict__ Wa, const float* __restrict__ Wb,
        const float* __restrict__ ba, const float* __restrict__ bb){
    int b = blockIdx.x;
    if (b < 125)
        proj_body<1,0>(b, g_rel, 1, 0, Wmsg, 192, 64, 128, g_pr, g_pq, 0, 0, 0);
    else if (b < 1149)
        proj_body<0,0>(b-125, g_node, 1, 0, Wmsg, 192, 0, 0, g_projA, 0, 0, 0, 0);
    else
        relscal_body(b-1149, Wa, Wb, ba, bb);
}

// stage4: Ph2+Pt2 (node, TWO) | Pq2 (rel)
__global__ __launch_bounds__(256, 3) void k_stage4(const float* __restrict__ Wht){
    int b = blockIdx.x;
    if (b < 1024)
        proj_body<1,0>(b, g_node, 1, 0, Wht, 192, 0, 64, g_projA, g_projB, 0, 0, 0);
    else
        proj_body<0,0>(b-1024, g_rel, 1, 0, Wht, 192, 128, 0, g_pq, 0, 0, 0, 0);
}

// stage3: node = LN(act(nacc @ We^T + be))
__global__ __launch_bounds__(256, 3) void k_stage3(const float* __restrict__ We,
        const float* __restrict__ be){
    proj_body<0,1>(blockIdx.x, g_nacc, 1, 0, We, 64, 0, 0, g_node, 0, be, 0, 0);
}

// stage6: rel = LN(act(racc @ Wr^T + br) + rel); finals[i] = rel
__global__ __launch_bounds__(256, 3) void k_stage6(const float* __restrict__ Wr,
        const float* __restrict__ br, float* __restrict__ finals_i){
    proj_body<0,1>(blockIdx.x, g_racc, 1, 0, Wr, 64, 0, 0, g_rel, 0, br, g_rel, finals_i);
}

// final: fin = LN(act(concat(finals) @ Wf^T + bf))   (K=192 via 3 chunks)
__global__ __launch_bounds__(256, 3) void k_final(const float* __restrict__ Wf,
        const float* __restrict__ bf){
    proj_body<0,1>(blockIdx.x, g_finals, 3, (size_t)RTT*HH, Wf, 192, 0, 0, g_fin, 0, bf, 0, 0);
}

// ---------------- fused attention segment sums ----------------
__global__ void k_absum(){
    if (blockIdx.x < 256){
        int n = blockIdx.x*256 + threadIdx.x;
        int b = g_off_n[n], e = g_off_n[n+1];
        float s = 0.f;
        for (int j = b; j < e; j++){
            int4 rc = g_recN[j];
            float a = __expf(g_Ar[rc.y] + g_Aq[rc.z]);
            g_aes[j] = a; s += a;
        }
        g_asum[n] = s;
    } else {
        int w = (blockIdx.x - 256)*8 + (threadIdx.x >> 5);
        int lane = threadIdx.x & 31;
        if (w >= RTT) return;
        int b = g_off_t[w], e = g_off_t[w+1];
        float br = g_Br[w];
        float s = 0.f;
        for (int j = b + lane; j < e; j += 32){
            int4 rc = g_recT[j];
            float bv = __expf(br + g_Bq[rc.z]);
            g_bes[j] = bv; s += bv;
        }
        #pragma unroll
        for (int o=16;o;o>>=1) s += __shfl_xor_sync(0xffffffffu,s,o);
        if (lane == 0) g_bsum[w] = s;
    }
}

// ---------------- edge message aggregation: warp per node (CSR) ----------------
__global__ void k_msg_agg(const int* __restrict__ row, const float* __restrict__ bmsg){
    int w = (blockIdx.x*blockDim.x + threadIdx.x) >> 5;
    int lane = threadIdx.x & 31;
    if (w >= NN) return;
    int b = g_off_n[w], e = g_off_n[w+1];
    float denom = g_asum[row[w]] + 1e-10f;    // faithful a_sum[row[row_e]]
    float sc0 = g_dinv2[w] / denom;
    float2 bm = *(const float2*)(bmsg + 2*lane);
    float ax = 0.f, ay = 0.f;
    for (int j = b; j < e; j++){
        int4 rc = g_recN[j];
        float coef = g_aes[j] * sc0 * g_dinv2[rc.x];
        float2 ph = *(const float2*)(g_projA + (size_t)rc.x*HH + 2*lane);
        float2 pr = *(const float2*)(g_pr    + (size_t)rc.y*HH + 2*lane);
        float2 pq = *(const float2*)(g_pq    + (size_t)rc.z*HH + 2*lane);
        ax += coef*actf(ph.x + pr.x + pq.x + bm.x);
        ay += coef*actf(ph.y + pr.y + pq.y + bm.y);
    }
    *(float2*)(g_nacc + (size_t)w*HH + 2*lane) = make_float2(ax, ay);
}

// ---------------- ht2r aggregation: warp per relation type (CSR) ----------------
__global__ void k_ht2r_agg(const int* __restrict__ et, const float* __restrict__ bht){
    int w = (blockIdx.x*blockDim.x + threadIdx.x) >> 5;
    int lane = threadIdx.x & 31;
    if (w >= RTT) return;
    int b = g_off_t[w], e = g_off_t[w+1];
    float inv_denom = 1.f / (g_bsum[et[w]] + 1e-10f);  // faithful b_sum[et[et_e]]
    float2 bm = *(const float2*)(bht + 2*lane);
    float ax = 0.f, ay = 0.f;
    for (int j = b; j < e; j++){
        int4 rc = g_recT[j];
        float coef = g_bes[j] * inv_denom;
        float2 ph = *(const float2*)(g_projA + (size_t)rc.x*HH + 2*lane);
        float2 pt = *(const float2*)(g_projB + (size_t)rc.y*HH + 2*lane);
        float2 pq = *(const float2*)(g_pq    + (size_t)rc.z*HH + 2*lane);
        ax += coef*actf(ph.x + pt.x + pq.x + bm.x);
        ay += coef*actf(ph.y + pt.y + pq.y + bm.y);
    }
    *(float2*)(g_racc + (size_t)w*HH + 2*lane) = make_float2(ax, ay);
}

// ---------------- loop update (40 rows) ----------------
__global__ void k_loop(const float* __restrict__ Wl, const float* __restrict__ bl){
    __shared__ float cat[128];
    __shared__ float ps[2], pq2[2];
    int q = blockIdx.x, t = threadIdx.x;   // 64 threads
    int qrow = g_qrows[q];
    float lv = g_loop[q*HH + t];
    cat[t] = lv;
    cat[64+t] = g_rel[qrow*HH + t];
    __syncthreads();
    float s = bl[t];
    #pragma unroll 8
    for (int k=0;k<128;k++) s = fmaf(cat[k], Wl[t*128+k], s);
    float y = lv + actf(s);
    float ss = y, sq = y*y;
    #pragma unroll
    for (int o=16;o;o>>=1){ ss += __shfl_xor_sync(0xffffffffu,ss,o); sq += __shfl_xor_sync(0xffffffffu,sq,o); }
    if ((t&31)==0){ ps[t>>5]=ss; pq2[t>>5]=sq; }
    __syncthreads();
    float S = ps[0]+ps[1], Q = pq2[0]+pq2[1];
    float m = S*(1.f/64.f);
    float var = Q*(1.f/64.f) - m*m;
    float inv = rsqrtf(var + 1e-5f);
    g_loop[q*HH + t] = (y-m)*inv;
}

// ---------------- output means ----------------
__global__ void k_mean(float* __restrict__ out){
    int idx = blockIdx.x*blockDim.x + threadIdx.x;
    if (idx >= 8*201*64) return;
    int h = idx & 63;
    int rb = idx >> 6;
    int r = rb % 201;
    int b = rb / 201;
    float s = 0.f;
    if (r < 200){
        #pragma unroll
        for (int s5=0;s5<5;s5++) s += g_fin[(b*1000 + s5*200 + r)*HH + h];
    } else {
        #pragma unroll
        for (int s5=0;s5<5;s5++) s += g_loop[(b*5 + s5)*HH + h];
    }
    out[idx] = s * 0.2f;
}

// ---------------- host ----------------
struct Ptrs {
    const int *ei,*et,*eq,*hp,*tp,*qr,*lab;
    const float *pos,*srel,*lemb,*Wmsg,*bmsg,*Wht,*bht,*Wa,*ba,*Wb,*bb,*Wl,*bl,*We,*be,*Wr,*br,*Wf,*bf;
};

static void resolve(void* const* d, const int* sz, int n, Ptrs& p){
    int gi, wi;
    if (sz[0] == 2*EN){
        gi = 0;
        wi = (n > 10 && sz[7] == 1 && sz[8] == 1 && sz[9] == 1) ? 10 : 7;
    } else {
        wi = 0; gi = 19;
    }
    p.ei  = (const int*)d[gi+0]; p.et = (const int*)d[gi+1]; p.eq = (const int*)d[gi+2];
    p.hp  = (const int*)d[gi+3]; p.tp = (const int*)d[gi+4]; p.qr = (const int*)d[gi+5];
    p.lab = (const int*)d[gi+6];
    p.pos  = (const float*)d[wi+0];  p.srel = (const float*)d[wi+1];  p.lemb = (const float*)d[wi+2];
    p.Wmsg = (const float*)d[wi+3];  p.bmsg = (const float*)d[wi+4];
    p.Wht  = (const float*)d[wi+5];  p.bht  = (const float*)d[wi+6];
    p.Wa   = (const float*)d[wi+7];  p.ba   = (const float*)d[wi+8];
    p.Wb   = (const float*)d[wi+9];  p.bb   = (const float*)d[wi+10];
    p.Wl   = (const float*)d[wi+11]; p.bl   = (const float*)d[wi+12];
    p.We   = (const float*)d[wi+13]; p.be   = (const float*)d[wi+14];
    p.Wr   = (const float*)d[wi+15]; p.br   = (const float*)d[wi+16];
    p.Wf   = (const float*)d[wi+17]; p.bf   = (const float*)d[wi+18];
}

extern "C" void kernel_launch(void* const* d_in, const int* in_sizes, int n_in,
                              void* d_out, int out_size){
    Ptrs p; resolve(d_in, in_sizes, n_in, p);
    const int* col = p.ei;
    const int* row = p.ei + EN;

    float* s_finals;
    cudaGetSymbolAddress((void**)&s_finals, g_finals);

    // ---- init + CSR build ----
    k_zero<<<RTT*HH/256,256>>>();
    k_node_init<<<NN*HH/256,256>>>(p.lab, p.pos);
    k_set_rows<<<(BQn*HH+255)/256,256>>>(p.hp, p.pos + 0*HH);
    k_set_rows<<<(BQn*HH+255)/256,256>>>(p.tp, p.pos + 1*HH);
    k_rel_init<<<(BQn*HH+255)/256,256>>>(p.qr, p.srel, p.lemb);
    k_hist<<<EN/256,256>>>(row, p.et);
    k_scan1<<<72,1024>>>();
    k_scan2<<<2,64>>>();
    k_scan3<<<72,1024>>>();
    k_scatter<<<EN/256,256>>>(col, row, p.et, p.eq);
    k_dinv2<<<NN/256,256>>>();

    for (int i = 0; i < 3; i++){
        const float* Wmsg = p.Wmsg + i*HH*192;
        const float* bmsg = p.bmsg + i*HH;
        const float* Wht  = p.Wht  + i*HH*192;
        const float* bht  = p.bht  + i*HH;

        k_stage1<<<2149,256>>>(Wmsg, p.Wa + i*128, p.Wb + i*128, p.ba + i, p.bb + i);
        k_absum<<<1256,256>>>();
        k_msg_agg<<<NN*32/256,256>>>(row, bmsg);
        k_stage3<<<1024,256>>>(p.We + i*HH*HH, p.be + i*HH);
        k_stage4<<<1149,256>>>(Wht);
        k_ht2r_agg<<<RTT*32/256,256>>>(p.et, bht);
        k_stage6<<<125,256>>>(p.Wr + i*HH*HH, p.br + i*HH, s_finals + i*RTT*HH);
        k_loop<<<BQn,64>>>(p.Wl + i*HH*128, p.bl + i*HH);
    }

    k_final<<<125,256>>>(p.Wf, p.bf);
    k_mean<<<(8*201*64+255)/256,256>>>((float*)d_out);
}

// round 5
// speedup vs baseline: 1.1416x; 1.0269x over previous
#include <cuda_runtime.h>
#include <math.h>

#define EN   262144
#define NN   65536
#define RTT  8000
#define HH   64
#define BQn  40
#define RRn  200
#define SLOPE 0.22916666666666666f

typedef unsigned long long ull;

// ---------------- device scratch (no allocs allowed) ----------------
__device__ float g_node[NN*HH], g_nacc[NN*HH], g_projA[NN*HH], g_projB[NN*HH];
__device__ float g_rel[RTT*HH], g_racc[RTT*HH], g_pr[RTT*HH], g_pq[RTT*HH];
__device__ float g_finals[3*RTT*HH], g_fin[RTT*HH];
__device__ float g_Ar[RTT], g_Aq[RTT], g_Br[RTT], g_Bq[RTT];
__device__ float g_asum[NN], g_bsum[RTT], g_dinv2[NN];
__device__ float g_aes[EN], g_bes[EN];
__device__ float g_loop[BQn*HH];
__device__ int   g_qrows[BQn];
__device__ int   g_cnt_n[NN], g_off_n[NN+1], g_cur_n[NN];
__device__ int   g_cnt_t[RTT], g_off_t[RTT+1], g_cur_t[RTT];
__device__ int   g_aux[128];
__device__ int4  g_recN[EN];   // (col, et, eq, 0) grouped by row
__device__ int4  g_recT[EN];   // (col, row, eq, 0) grouped by edge_type

__device__ __forceinline__ float actf(float x){ return x >= 0.f ? x : x*SLOPE; }

__device__ __forceinline__ ull pk2(float x, float y){
    ull r; asm("mov.b64 %0, {%1, %2};" : "=l"(r) : "f"(x), "f"(y)); return r;
}
__device__ __forceinline__ void upk2(ull v, float& x, float& y){
    asm("mov.b64 {%0, %1}, %2;" : "=f"(x), "=f"(y) : "l"(v));
}
__device__ __forceinline__ void ffma2(ull& d, ull a, ull b){
    asm("fma.rn.f32x2 %0, %1, %2, %0;" : "+l"(d) : "l"(a), "l"(b));
}

// ---------------- init kernels ----------------
__global__ void k_zero(){
    int i = blockIdx.x*blockDim.x + threadIdx.x;
    if (i < RTT*HH) g_rel[i] = 0.f;
    if (i < NN)     g_cnt_n[i] = 0;
    if (i < RTT)    g_cnt_t[i] = 0;
}

// node init (with h/t membership) + rel q-rows + loop init
__global__ void k_init(const int* __restrict__ labels, const float* __restrict__ pos_emb,
                       const int* __restrict__ hp, const int* __restrict__ tp,
                       const int* __restrict__ qrel, const float* __restrict__ srel,
                       const float* __restrict__ lemb){
    int t = threadIdx.x;
    if (blockIdx.x < NN*HH/256){
        __shared__ int shp[BQn], stp[BQn], ssrc[4];
        if (t < BQn) shp[t] = hp[t];
        else if (t < 2*BQn) stp[t-BQn] = tp[t-BQn];
        __syncthreads();
        if (t < 4){
            int n = blockIdx.x*4 + t;
            int s = -1;
            #pragma unroll
            for (int q = 0; q < BQn; q++) if (shp[q] == n) s = 0;
            #pragma unroll
            for (int q = 0; q < BQn; q++) if (stp[q] == n) s = 1;  // t overrides h
            ssrc[t] = s;
        }
        __syncthreads();
        int idx = blockIdx.x*256 + t;
        int n = idx >> 6, h = idx & 63;
        int src = ssrc[(idx >> 6) & 3];
        float v;
        if (src < 0){
            int pp = labels[2*n]*4 + labels[2*n+1];
            v = pos_emb[pp*HH + h];
        } else {
            v = pos_emb[src*HH + h];
        }
        g_node[idx] = v;
    } else {
        int idx = (blockIdx.x - NN*HH/256)*256 + t;   // 0..2559 = BQn*HH
        int q = idx >> 6, h = idx & 63;
        int qrow = qrel[q] + q*RRn;
        if (h == 0) g_qrows[q] = qrow;
        g_rel[qrow*HH + h] = srel[h];
        g_loop[idx] = lemb[h];
    }
}

// ---------------- CSR build ----------------
__global__ void k_hist(const int* __restrict__ row, const int* __restrict__ et){
    int e = blockIdx.x*blockDim.x + threadIdx.x;
    if (e >= EN) return;
    atomicAdd(&g_cnt_n[row[e]], 1);
    atomicAdd(&g_cnt_t[et[e]], 1);
}

__device__ __forceinline__ void scan1_body(const int* cnt, int* off, int* aux, int n, int blk){
    __shared__ int sh[1024];
    int t = threadIdx.x, i = blk*1024 + t;
    int v = (i < n) ? cnt[i] : 0;
    sh[t] = v; __syncthreads();
    for (int d = 1; d < 1024; d <<= 1){
        int u = (t >= d) ? sh[t-d] : 0;
        __syncthreads();
        sh[t] += u;
        __syncthreads();
    }
    if (i < n) off[i] = sh[t] - v;
    if (t == 1023) aux[blk] = sh[t];
}

__global__ void k_scan1(){
    if (blockIdx.x < 64) scan1_body(g_cnt_n, g_off_n, g_aux, NN, blockIdx.x);
    else                 scan1_body(g_cnt_t, g_off_t, g_aux + 64, RTT, blockIdx.x - 64);
}

__global__ void k_scan2(){
    __shared__ int sh[64];
    int t = threadIdx.x;
    int* aux = blockIdx.x ? (g_aux + 64) : g_aux;
    int m = blockIdx.x ? 8 : 64;
    int v = (t < m) ? aux[t] : 0;
    sh[t] = v; __syncthreads();
    for (int d = 1; d < 64; d <<= 1){
        int u = (t >= d) ? sh[t-d] : 0;
        __syncthreads();
        sh[t] += u;
        __syncthreads();
    }
    if (t < m) aux[t] = sh[t] - v;  // exclusive
}

__global__ void k_scan3(){
    int t = threadIdx.x;
    if (blockIdx.x < 64){
        int i = blockIdx.x*1024 + t;
        int o = g_off_n[i] + g_aux[blockIdx.x];
        g_off_n[i] = o; g_cur_n[i] = o;
        int c = g_cnt_n[i];
        g_dinv2[i] = c > 0 ? 1.f/(float)c : 0.f;
        if (i == 0) g_off_n[NN] = EN;
    } else {
        int b2 = blockIdx.x - 64;
        int i = b2*1024 + t;
        if (i < RTT){
            int o = g_off_t[i] + g_aux[64 + b2];
            g_off_t[i] = o; g_cur_t[i] = o;
        }
        if (i == 0) g_off_t[RTT] = EN;
    }
}

// ---------------- per-relation attention scalars (standalone body, layer 0) ----------------
__device__ __forceinline__ void relscal_body(int b2, const float* __restrict__ Wa,
        const float* __restrict__ Wb, const float* __restrict__ ba, const float* __restrict__ bb){
    int w = b2*8 + (threadIdx.x >> 5);
    int lane = threadIdx.x & 31;
    if (w >= RTT) return;
    float2 v = *(const float2*)(g_rel + (size_t)w*HH + 2*lane);
    float a0 = actf(v.x), a1 = actf(v.y);
    float2 wa1 = *(const float2*)(Wa + 2*lane);
    float2 wa2 = *(const float2*)(Wa + 64 + 2*lane);
    float2 wb1 = *(const float2*)(Wb + 2*lane);
    float2 wb2 = *(const float2*)(Wb + 64 + 2*lane);
    float sar = a0*wa1.x + a1*wa1.y;
    float saq = a0*wa2.x + a1*wa2.y;
    float sbr = v.x*wb1.x + v.y*wb1.y;
    float sbq = v.x*wb2.x + v.y*wb2.y;
    #pragma unroll
    for (int o=16;o;o>>=1){
        sar += __shfl_xor_sync(0xffffffffu,sar,o);
        saq += __shfl_xor_sync(0xffffffffu,saq,o);
        sbr += __shfl_xor_sync(0xffffffffu,sbr,o);
        sbq += __shfl_xor_sync(0xffffffffu,sbq,o);
    }
    if (lane == 0){ g_Ar[w]=sar+ba[0]; g_Aq[w]=saq; g_Br[w]=sbr+bb[0]; g_Bq[w]=sbq; }
}

__global__ void k_scatter(const int* __restrict__ col, const int* __restrict__ row,
                          const int* __restrict__ et, const int* __restrict__ eq,
                          const float* __restrict__ Wa0, const float* __restrict__ Wb0,
                          const float* __restrict__ ba0, const float* __restrict__ bb0){
    int b = blockIdx.x;
    if (b < 1024){
        int e = b*blockDim.x + threadIdx.x;
        if (e >= EN) return;
        int c = col[e], r = row[e], t = et[e], q = eq[e];
        int p  = atomicAdd(&g_cur_n[r], 1);
        g_recN[p] = make_int4(c, t, q, 0);
        int p2 = atomicAdd(&g_cur_t[t], 1);
        g_recT[p2] = make_int4(c, r, q, 0);
    } else {
        relscal_body(b - 1024, Wa0, Wb0, ba0, bb0);   // layer-0 attention scalars
    }
}

// ---------------- core proj body: conflict-free smem, optional LN + scal epilogue ----------------
template<int TWO, int DOLN, int DOSCAL>
__device__ __forceinline__ void proj_body(
        int blk, const float* __restrict__ in, int nchunk, size_t cstride,
        const float* __restrict__ W, int wstride, int co1, int co2,
        float* __restrict__ out1, float* __restrict__ out2,
        const float* __restrict__ bias, const float* __restrict__ resid,
        float* __restrict__ outB,
        const float* __restrict__ Wa2, const float* __restrict__ Wb2,
        const float* __restrict__ ba2, const float* __restrict__ bb2)
{
    __shared__ float In[64][68];
    __shared__ float Wt[TWO+1][32][66];
    const int t = threadIdx.x;
    const int op = t & 31, rg = t >> 5;
    const size_t rowbase = (size_t)blk * 64;

    ull A0[4], B0[4], A1[4], B1[4];
    {
        ull z = pk2(0.f, 0.f);
        #pragma unroll
        for (int j=0;j<4;j++){ A0[j]=z; B0[j]=z; A1[j]=z; B1[j]=z; }
    }

    for (int c = 0; c < nchunk; c++){
        #pragma unroll 1
        for (int h = 0; h < 2; h++){
            __syncthreads();
            if (h == 0){
                const float* inc = in + (size_t)c*cstride + rowbase*HH;
                for (int idx = t; idx < 1024; idx += 256){
                    int r = idx & 63, kq = idx >> 6;
                    float4 v = *(const float4*)(inc + (size_t)r*HH + 4*kq);
                    In[4*kq+0][r]=v.x; In[4*kq+1][r]=v.y;
                    In[4*kq+2][r]=v.z; In[4*kq+3][r]=v.w;
                }
            }
            {
                int cob = c*64 + h*32;
                for (int idx = t; idx < 2048; idx += 256){
                    int o = idx >> 5, k = idx & 31;
                    Wt[0][k][o] = W[o*wstride + co1 + cob + k];
                    if (TWO) Wt[TWO][k][o] = W[o*wstride + co2 + cob + k];
                }
            }
            __syncthreads();
            #pragma unroll 8
            for (int k = 0; k < 32; k++){
                ulonglong2 v01 = *(const ulonglong2*)&In[h*32+k][rg*8];
                ulonglong2 v23 = *(const ulonglong2*)&In[h*32+k][rg*8+4];
                float2 w0 = *(const float2*)&Wt[0][k][2*op];
                ull wa = pk2(w0.x, w0.x), wb = pk2(w0.y, w0.y);
                ffma2(A0[0], v01.x, wa); ffma2(A0[1], v01.y, wa);
                ffma2(A0[2], v23.x, wa); ffma2(A0[3], v23.y, wa);
                ffma2(B0[0], v01.x, wb); ffma2(B0[1], v01.y, wb);
                ffma2(B0[2], v23.x, wb); ffma2(B0[3], v23.y, wb);
                if (TWO){
                    float2 w1 = *(const float2*)&Wt[TWO][k][2*op];
                    ull wc = pk2(w1.x, w1.x), wd = pk2(w1.y, w1.y);
                    ffma2(A1[0], v01.x, wc); ffma2(A1[1], v01.y, wc);
                    ffma2(A1[2], v23.x, wc); ffma2(A1[3], v23.y, wc);
                    ffma2(B1[0], v01.x, wd); ffma2(B1[1], v01.y, wd);
                    ffma2(B1[2], v23.x, wd); ffma2(B1[3], v23.y, wd);
                }
            }
        }
    }

    if (!DOLN){
        #pragma unroll
        for (int j = 0; j < 4; j++){
            size_t r0 = rowbase + rg*8 + 2*j;
            float a0,a1,b0,b1;
            upk2(A0[j], a0, a1); upk2(B0[j], b0, b1);
            *(float2*)(out1 + r0*HH + 2*op)     = make_float2(a0, b0);
            *(float2*)(out1 + (r0+1)*HH + 2*op) = make_float2(a1, b1);
            if (TWO){
                upk2(A1[j], a0, a1); upk2(B1[j], b0, b1);
                *(float2*)(out2 + r0*HH + 2*op)     = make_float2(a0, b0);
                *(float2*)(out2 + (r0+1)*HH + 2*op) = make_float2(a1, b1);
            }
        }
    } else {
        float2 bv = *(const float2*)(bias + 2*op);
        float2 wa1, wav2, wb1, wbv2;
        bool doscal = DOSCAL && (Wa2 != 0);
        if (DOSCAL && doscal){
            wa1  = *(const float2*)(Wa2 + 2*op);
            wav2 = *(const float2*)(Wa2 + 64 + 2*op);
            wb1  = *(const float2*)(Wb2 + 2*op);
            wbv2 = *(const float2*)(Wb2 + 64 + 2*op);
        }
        #pragma unroll
        for (int j = 0; j < 4; j++){
            size_t r0 = rowbase + rg*8 + 2*j;
            float a0,a1,b0,b1;
            upk2(A0[j], a0, a1); upk2(B0[j], b0, b1);
            float y00 = actf(a0 + bv.x), y01 = actf(b0 + bv.y);
            float y10 = actf(a1 + bv.x), y11 = actf(b1 + bv.y);
            if (resid){
                float2 rv0 = *(const float2*)(resid + r0*HH + 2*op);
                float2 rv1 = *(const float2*)(resid + (r0+1)*HH + 2*op);
                y00 += rv0.x; y01 += rv0.y; y10 += rv1.x; y11 += rv1.y;
            }
            float s0 = y00+y01, q0 = y00*y00+y01*y01;
            float s1 = y10+y11, q1 = y10*y10+y11*y11;
            #pragma unroll
            for (int o=16;o;o>>=1){
                s0 += __shfl_xor_sync(0xffffffffu,s0,o);
                q0 += __shfl_xor_sync(0xffffffffu,q0,o);
                s1 += __shfl_xor_sync(0xffffffffu,s1,o);
                q1 += __shfl_xor_sync(0xffffffffu,q1,o);
            }
            float m0 = s0*(1.f/64.f), m1 = s1*(1.f/64.f);
            float i0 = rsqrtf(q0*(1.f/64.f) - m0*m0 + 1e-5f);
            float i1 = rsqrtf(q1*(1.f/64.f) - m1*m1 + 1e-5f);
            float2 w0 = make_float2((y00-m0)*i0, (y01-m0)*i0);
            float2 w1 = make_float2((y10-m1)*i1, (y11-m1)*i1);
            *(float2*)(out1 + r0*HH + 2*op)     = w0;
            *(float2*)(out1 + (r0+1)*HH + 2*op) = w1;
            if (outB){
                *(float2*)(outB + r0*HH + 2*op)     = w0;
                *(float2*)(outB + (r0+1)*HH + 2*op) = w1;
            }
            if (DOSCAL && doscal){
                // per-row attention scalars for the NEXT layer
                float pa0 = actf(w0.x)*wa1.x + actf(w0.y)*wa1.y;
                float pq0 = actf(w0.x)*wav2.x + actf(w0.y)*wav2.y;
                float pb0 = w0.x*wb1.x + w0.y*wb1.y;
                float pc0 = w0.x*wbv2.x + w0.y*wbv2.y;
                float pa1 = actf(w1.x)*wa1.x + actf(w1.y)*wa1.y;
                float pq1 = actf(w1.x)*wav2.x + actf(w1.y)*wav2.y;
                float pb1 = w1.x*wb1.x + w1.y*wb1.y;
                float pc1 = w1.x*wbv2.x + w1.y*wbv2.y;
                #pragma unroll
                for (int o=16;o;o>>=1){
                    pa0 += __shfl_xor_sync(0xffffffffu,pa0,o);
                    pq0 += __shfl_xor_sync(0xffffffffu,pq0,o);
                    pb0 += __shfl_xor_sync(0xffffffffu,pb0,o);
                    pc0 += __shfl_xor_sync(0xffffffffu,pc0,o);
                    pa1 += __shfl_xor_sync(0xffffffffu,pa1,o);
                    pq1 += __shfl_xor_sync(0xffffffffu,pq1,o);
                    pb1 += __shfl_xor_sync(0xffffffffu,pb1,o);
                    pc1 += __shfl_xor_sync(0xffffffffu,pc1,o);
                }
                if (op == 0){
                    g_Ar[r0]   = pa0 + ba2[0]; g_Aq[r0]   = pq0;
                    g_Br[r0]   = pb0 + bb2[0]; g_Bq[r0]   = pc0;
                    g_Ar[r0+1] = pa1 + ba2[0]; g_Aq[r0+1] = pq1;
                    g_Br[r0+1] = pb1 + bb2[0]; g_Bq[r0+1] = pc1;
                }
            }
        }
    }
}

// ---------------- attention segment sums (body) ----------------
__device__ __forceinline__ void absum_body(int b2){
    if (b2 < 256){
        int n = b2*256 + threadIdx.x;
        int b = g_off_n[n], e = g_off_n[n+1];
        float s = 0.f;
        for (int j = b; j < e; j++){
            int4 rc = g_recN[j];
            float a = __expf(g_Ar[rc.y] + g_Aq[rc.z]);
            g_aes[j] = a; s += a;
        }
        g_asum[n] = s;
    } else {
        int w = (b2 - 256)*8 + (threadIdx.x >> 5);
        int lane = threadIdx.x & 31;
        if (w >= RTT) return;
        int b = g_off_t[w], e = g_off_t[w+1];
        float br = g_Br[w];
        float s = 0.f;
        for (int j = b + lane; j < e; j += 32){
            int4 rc = g_recT[j];
            float bv = __expf(br + g_Bq[rc.z]);
            g_bes[j] = bv; s += bv;
        }
        #pragma unroll
        for (int o=16;o;o>>=1) s += __shfl_xor_sync(0xffffffffu,s,o);
        if (lane == 0) g_bsum[w] = s;
    }
}

// ---------------- loop update: one warp per query ----------------
__device__ __forceinline__ void loop_warp(int q, const float* __restrict__ Wl,
                                          const float* __restrict__ bl){
    int lane = threadIdx.x & 31;
    int qrow = g_qrows[q];
    float2 lv = *(const float2*)(g_loop + q*HH + 2*lane);
    float s0 = bl[2*lane], s1 = bl[2*lane+1];
    const float* lrow = g_loop + q*HH;
    const float* rrow = g_rel + (size_t)qrow*HH;
    const float* w0p = Wl + (size_t)(2*lane)*128;
    const float* w1p = w0p + 128;
    #pragma unroll 8
    for (int k = 0; k < 64; k++){
        float c = lrow[k];
        s0 = fmaf(c, w0p[k], s0); s1 = fmaf(c, w1p[k], s1);
    }
    #pragma unroll 8
    for (int k = 0; k < 64; k++){
        float c = rrow[k];
        s0 = fmaf(c, w0p[64+k], s0); s1 = fmaf(c, w1p[64+k], s1);
    }
    float y0 = lv.x + actf(s0), y1 = lv.y + actf(s1);
    float ss = y0+y1, sq = y0*y0+y1*y1;
    #pragma unroll
    for (int o=16;o;o>>=1){
        ss += __shfl_xor_sync(0xffffffffu,ss,o);
        sq += __shfl_xor_sync(0xffffffffu,sq,o);
    }
    float m = ss*(1.f/64.f);
    float inv = rsqrtf(sq*(1.f/64.f) - m*m + 1e-5f);
    *(float2*)(g_loop + q*HH + 2*lane) = make_float2((y0-m)*inv, (y1-m)*inv);
}

// ---------------- stage kernels ----------------
// stage1: Pr+Pq (rel, TWO) | Ph (node) | absum | loop(prev layer)
__global__ __launch_bounds__(256, 3) void k_stage1(const float* __restrict__ Wmsg,
        const float* __restrict__ Wl_prev, const float* __restrict__ bl_prev){
    int b = blockIdx.x;
    if (b < 125)
        proj_body<1,0,0>(b, g_rel, 1, 0, Wmsg, 192, 64, 128, g_pr, g_pq, 0, 0, 0, 0,0,0,0);
    else if (b < 1149)
        proj_body<0,0,0>(b-125, g_node, 1, 0, Wmsg, 192, 0, 0, g_projA, 0, 0, 0, 0, 0,0,0,0);
    else if (b < 2405)
        absum_body(b-1149);
    else {
        if (threadIdx.x < 32) loop_warp(b-2405, Wl_prev, bl_prev);
    }
}

// stage4: Ph2+Pt2 (node, TWO) | Pq2 (rel)
__global__ __launch_bounds__(256, 3) void k_stage4(const float* __restrict__ Wht){
    int b = blockIdx.x;
    if (b < 1024)
        proj_body<1,0,0>(b, g_node, 1, 0, Wht, 192, 0, 64, g_projA, g_projB, 0, 0, 0, 0,0,0,0);
    else
        proj_body<0,0,0>(b-1024, g_rel, 1, 0, Wht, 192, 128, 0, g_pq, 0, 0, 0, 0, 0,0,0,0);
}

// stage3: node = LN(act(nacc @ We^T + be))
__global__ __launch_bounds__(256, 3) void k_stage3(const float* __restrict__ We,
        const float* __restrict__ be){
    proj_body<0,1,0>(blockIdx.x, g_nacc, 1, 0, We, 64, 0, 0, g_node, 0, be, 0, 0, 0,0,0,0);
}

// stage6: rel = LN(act(racc @ Wr^T + br) + rel); finals[i] = rel; + next-layer relscal
__global__ __launch_bounds__(256, 3) void k_stage6(const float* __restrict__ Wr,
        const float* __restrict__ br, float* __restrict__ finals_i,
        const float* __restrict__ Wa2, const float* __restrict__ Wb2,
        const float* __restrict__ ba2, const float* __restrict__ bb2){
    proj_body<0,1,1>(blockIdx.x, g_racc, 1, 0, Wr, 64, 0, 0, g_rel, 0, br, g_rel, finals_i,
                     Wa2, Wb2, ba2, bb2);
}

// final: fin = LN(act(concat(finals) @ Wf^T + bf)) | loop(layer 2)
__global__ __launch_bounds__(256, 3) void k_final(const float* __restrict__ Wf,
        const float* __restrict__ bf, const float* __restrict__ Wl2,
        const float* __restrict__ bl2){
    int b = blockIdx.x;
    if (b < 125)
        proj_body<0,1,0>(b, g_finals, 3, (size_t)RTT*HH, Wf, 192, 0, 0, g_fin, 0, bf, 0, 0, 0,0,0,0);
    else {
        if (threadIdx.x < 32) loop_warp(b-125, Wl2, bl2);
    }
}

// ---------------- edge message aggregation: warp per node (CSR) ----------------
__global__ void k_msg_agg(const int* __restrict__ row, const float* __restrict__ bmsg){
    int w = (blockIdx.x*blockDim.x + threadIdx.x) >> 5;
    int lane = threadIdx.x & 31;
    if (w >= NN) return;
    int b = g_off_n[w], e = g_off_n[w+1];
    float denom = g_asum[row[w]] + 1e-10f;    // faithful a_sum[row[row_e]]
    float sc0 = g_dinv2[w] / denom;
    float2 bm = *(const float2*)(bmsg + 2*lane);
    float ax = 0.f, ay = 0.f;
    for (int j = b; j < e; j++){
        int4 rc = g_recN[j];
        float coef = g_aes[j] * sc0 * g_dinv2[rc.x];
        float2 ph = *(const float2*)(g_projA + (size_t)rc.x*HH + 2*lane);
        float2 pr = *(const float2*)(g_pr    + (size_t)rc.y*HH + 2*lane);
        float2 pq = *(const float2*)(g_pq    + (size_t)rc.z*HH + 2*lane);
        ax += coef*actf(ph.x + pr.x + pq.x + bm.x);
        ay += coef*actf(ph.y + pr.y + pq.y + bm.y);
    }
    *(float2*)(g_nacc + (size_t)w*HH + 2*lane) = make_float2(ax, ay);
}

// ---------------- ht2r aggregation: warp per relation type (CSR) ----------------
__global__ void k_ht2r_agg(const int* __restrict__ et, const float* __restrict__ bht){
    int w = (blockIdx.x*blockDim.x + threadIdx.x) >> 5;
    int lane = threadIdx.x & 31;
    if (w >= RTT) return;
    int b = g_off_t[w], e = g_off_t[w+1];
    float inv_denom = 1.f / (g_bsum[et[w]] + 1e-10f);  // faithful b_sum[et[et_e]]
    float2 bm = *(const float2*)(bht + 2*lane);
    float ax = 0.f, ay = 0.f;
    for (int j = b; j < e; j++){
        int4 rc = g_recT[j];
        float coef = g_bes[j] * inv_denom;
        float2 ph = *(const float2*)(g_projA + (size_t)rc.x*HH + 2*lane);
        float2 pt = *(const float2*)(g_projB + (size_t)rc.y*HH + 2*lane);
        float2 pq = *(const float2*)(g_pq    + (size_t)rc.z*HH + 2*lane);
        ax += coef*actf(ph.x + pt.x + pq.x + bm.x);
        ay += coef*actf(ph.y + pt.y + pq.y + bm.y);
    }
    *(float2*)(g_racc + (size_t)w*HH + 2*lane) = make_float2(ax, ay);
}

// ---------------- output means ----------------
__global__ void k_mean(float* __restrict__ out){
    int idx = blockIdx.x*blockDim.x + threadIdx.x;
    if (idx >= 8*201*64) return;
    int h = idx & 63;
    int rb = idx >> 6;
    int r = rb % 201;
    int b = rb / 201;
    float s = 0.f;
    if (r < 200){
        #pragma unroll
        for (int s5=0;s5<5;s5++) s += g_fin[(b*1000 + s5*200 + r)*HH + h];
    } else {
        #pragma unroll
        for (int s5=0;s5<5;s5++) s += g_loop[(b*5 + s5)*HH + h];
    }
    out[idx] = s * 0.2f;
}

// ---------------- host ----------------
struct Ptrs {
    const int *ei,*et,*eq,*hp,*tp,*qr,*lab;
    const float *pos,*srel,*lemb,*Wmsg,*bmsg,*Wht,*bht,*Wa,*ba,*Wb,*bb,*Wl,*bl,*We,*be,*Wr,*br,*Wf,*bf;
};

static void resolve(void* const* d, const int* sz, int n, Ptrs& p){
    int gi, wi;
    if (sz[0] == 2*EN){
        gi = 0;
        wi = (n > 10 && sz[7] == 1 && sz[8] == 1 && sz[9] == 1) ? 10 : 7;
    } else {
        wi = 0; gi = 19;
    }
    p.ei  = (const int*)d[gi+0]; p.et = (const int*)d[gi+1]; p.eq = (const int*)d[gi+2];
    p.hp  = (const int*)d[gi+3]; p.tp = (const int*)d[gi+4]; p.qr = (const int*)d[gi+5];
    p.lab = (const int*)d[gi+6];
    p.pos  = (const float*)d[wi+0];  p.srel = (const float*)d[wi+1];  p.lemb = (const float*)d[wi+2];
    p.Wmsg = (const float*)d[wi+3];  p.bmsg = (const float*)d[wi+4];
    p.Wht  = (const float*)d[wi+5];  p.bht  = (const float*)d[wi+6];
    p.Wa   = (const float*)d[wi+7];  p.ba   = (const float*)d[wi+8];
    p.Wb   = (const float*)d[wi+9];  p.bb   = (const float*)d[wi+10];
    p.Wl   = (const float*)d[wi+11]; p.bl   = (const float*)d[wi+12];
    p.We   = (const float*)d[wi+13]; p.be   = (const float*)d[wi+14];
    p.Wr   = (const float*)d[wi+15]; p.br   = (const float*)d[wi+16];
    p.Wf   = (const float*)d[wi+17]; p.bf   = (const float*)d[wi+18];
}

extern "C" void kernel_launch(void* const* d_in, const int* in_sizes, int n_in,
                              void* d_out, int out_size){
    Ptrs p; resolve(d_in, in_sizes, n_in, p);
    const int* col = p.ei;
    const int* row = p.ei + EN;

    float* s_finals;
    cudaGetSymbolAddress((void**)&s_finals, g_finals);

    // ---- init + CSR build ----
    k_zero<<<RTT*HH/256,256>>>();
    k_init<<<NN*HH/256 + BQn*HH/256,256>>>(p.lab, p.pos, p.hp, p.tp, p.qr, p.srel, p.lemb);
    k_hist<<<EN/256,256>>>(row, p.et);
    k_scan1<<<72,1024>>>();
    k_scan2<<<2,64>>>();
    k_scan3<<<72,1024>>>();
    k_scatter<<<2024,256>>>(col, row, p.et, p.eq, p.Wa, p.Wb, p.ba, p.bb);

    for (int i = 0; i < 3; i++){
        const float* Wmsg = p.Wmsg + i*HH*192;
        const float* bmsg = p.bmsg + i*HH;
        const float* Wht  = p.Wht  + i*HH*192;
        const float* bht  = p.bht  + i*HH;
        // next-layer attention weights for stage6 epilogue (null for last layer)
        const float* Wa2 = (i < 2) ? (p.Wa + (i+1)*128) : (const float*)0;
        const float* Wb2 = (i < 2) ? (p.Wb + (i+1)*128) : (const float*)0;
        const float* ba2 = (i < 2) ? (p.ba + (i+1)) : (const float*)0;
        const float* bb2 = (i < 2) ? (p.bb + (i+1)) : (const float*)0;

        int s1_blocks = (i == 0) ? 2405 : 2445;   // loop(prev) rides along for i>=1
        const float* Wlp = (i >= 1) ? (p.Wl + (i-1)*HH*128) : p.Wl;
        const float* blp = (i >= 1) ? (p.bl + (i-1)*HH) : p.bl;

        k_stage1<<<s1_blocks,256>>>(Wmsg, Wlp, blp);
        k_msg_agg<<<NN*32/256,256>>>(row, bmsg);
        k_stage3<<<1024,256>>>(p.We + i*HH*HH, p.be + i*HH);
        k_stage4<<<1149,256>>>(Wht);
        k_ht2r_agg<<<RTT*32/256,256>>>(p.et, bht);
        k_stage6<<<125,256>>>(p.Wr + i*HH*HH, p.br + i*HH, s_finals + i*RTT*HH,
                              Wa2, Wb2, ba2, bb2);
    }

    k_final<<<165,256>>>(p.Wf, p.bf, p.Wl + 2*HH*128, p.bl + 2*HH);
    k_mean<<<(8*201*64+255)/256,256>>>((float*)d_out);
}

// round 6
// speedup vs baseline: 1.2926x; 1.1323x over previous
#include <cuda_runtime.h>
#include <cuda_fp16.h>
#include <math.h>

#define EN   262144
#define NN   65536
#define RTT  8000
#define HH   64
#define BQn  40
#define RRn  200
#define SLOPE 0.22916666666666666f

typedef unsigned long long ull;

// ---------------- device scratch (no allocs allowed) ----------------
__device__ float  g_node[NN*HH], g_nacc[NN*HH];
__device__ __half g_projAh[NN*HH], g_projBh[NN*HH];
__device__ __half g_prh[RTT*HH], g_pqh[RTT*HH], g_pq2h[RTT*HH];
__device__ float  g_rel[RTT*HH], g_racc[RTT*HH];
__device__ float  g_finals[3*RTT*HH], g_fin[RTT*HH];
__device__ float  g_Ar[RTT], g_Aq[RTT], g_Br[RTT], g_Bq[RTT];
__device__ float  g_asum[NN], g_bsum[RTT], g_dinv2[NN];
__device__ float  g_aes[EN], g_bes[EN];
__device__ float  g_loop[BQn*HH];
__device__ int    g_qrows[BQn];
__device__ int    g_cnt_n[NN], g_off_n[NN+1], g_cur_n[NN];
__device__ int    g_cnt_t[RTT], g_off_t[RTT+1], g_cur_t[RTT];
__device__ int    g_aux[128];
__device__ int4   g_recN[EN];   // (col, et, eq, 0) grouped by row
__device__ int4   g_recT[EN];   // (col, row, eq, 0) grouped by edge_type

__device__ __forceinline__ float actf(float x){ return x >= 0.f ? x : x*SLOPE; }

__device__ __forceinline__ ull pk2(float x, float y){
    ull r; asm("mov.b64 %0, {%1, %2};" : "=l"(r) : "f"(x), "f"(y)); return r;
}
__device__ __forceinline__ void upk2(ull v, float& x, float& y){
    asm("mov.b64 {%0, %1}, %2;" : "=f"(x), "=f"(y) : "l"(v));
}
__device__ __forceinline__ void ffma2(ull& d, ull a, ull b){
    asm("fma.rn.f32x2 %0, %1, %2, %0;" : "+l"(d) : "l"(a), "l"(b));
}

// ---------------- init + hist (fused; relies on tail-zeroing from prior call) ----------------
#define INIT_NODE_BLK (NN*HH/256)          // 16384
#define INIT_REL_BLK  (BQn*HH/256)         // 10
#define INIT_HIST_BLK (EN/256)             // 1024
__global__ void k_inithist(const int* __restrict__ labels, const float* __restrict__ pos_emb,
                           const int* __restrict__ hp, const int* __restrict__ tp,
                           const int* __restrict__ qrel, const float* __restrict__ srel,
                           const float* __restrict__ lemb,
                           const int* __restrict__ row, const int* __restrict__ et){
    int t = threadIdx.x;
    int b = blockIdx.x;
    if (b < INIT_NODE_BLK){
        __shared__ int shp[BQn], stp[BQn], ssrc[4];
        if (t < BQn) shp[t] = hp[t];
        else if (t < 2*BQn) stp[t-BQn] = tp[t-BQn];
        __syncthreads();
        if (t < 4){
            int n = b*4 + t;
            int s = -1;
            #pragma unroll
            for (int q = 0; q < BQn; q++) if (shp[q] == n) s = 0;
            #pragma unroll
            for (int q = 0; q < BQn; q++) if (stp[q] == n) s = 1;  // t overrides h
            ssrc[t] = s;
        }
        __syncthreads();
        int idx = b*256 + t;
        int n = idx >> 6, h = idx & 63;
        int src = ssrc[(idx >> 6) & 3];
        float v;
        if (src < 0){
            int pp = labels[2*n]*4 + labels[2*n+1];
            v = pos_emb[pp*HH + h];
        } else {
            v = pos_emb[src*HH + h];
        }
        g_node[idx] = v;
    } else if (b < INIT_NODE_BLK + INIT_REL_BLK){
        int idx = (b - INIT_NODE_BLK)*256 + t;
        int q = idx >> 6, h = idx & 63;
        int qrow = qrel[q] + q*RRn;
        if (h == 0) g_qrows[q] = qrow;
        g_rel[qrow*HH + h] = srel[h];   // rest of g_rel zeroed by prior call's k_mean tail
        g_loop[idx] = lemb[h];
    } else {
        int e = (b - INIT_NODE_BLK - INIT_REL_BLK)*256 + t;
        atomicAdd(&g_cnt_n[row[e]], 1);
        atomicAdd(&g_cnt_t[et[e]], 1);
    }
}

// ---------------- CSR scans ----------------
__device__ __forceinline__ void scan1_body(const int* cnt, int* off, int* aux, int n, int blk){
    __shared__ int sh[1024];
    int t = threadIdx.x, i = blk*1024 + t;
    int v = (i < n) ? cnt[i] : 0;
    sh[t] = v; __syncthreads();
    for (int d = 1; d < 1024; d <<= 1){
        int u = (t >= d) ? sh[t-d] : 0;
        __syncthreads();
        sh[t] += u;
        __syncthreads();
    }
    if (i < n) off[i] = sh[t] - v;
    if (t == 1023) aux[blk] = sh[t];
}

__global__ void k_scan1(){
    if (blockIdx.x < 64) scan1_body(g_cnt_n, g_off_n, g_aux, NN, blockIdx.x);
    else                 scan1_body(g_cnt_t, g_off_t, g_aux + 64, RTT, blockIdx.x - 64);
}

__global__ void k_scan2(){
    __shared__ int sh[64];
    int t = threadIdx.x;
    int* aux = blockIdx.x ? (g_aux + 64) : g_aux;
    int m = blockIdx.x ? 8 : 64;
    int v = (t < m) ? aux[t] : 0;
    sh[t] = v; __syncthreads();
    for (int d = 1; d < 64; d <<= 1){
        int u = (t >= d) ? sh[t-d] : 0;
        __syncthreads();
        sh[t] += u;
        __syncthreads();
    }
    if (t < m) aux[t] = sh[t] - v;  // exclusive
}

__global__ void k_scan3(){
    int t = threadIdx.x;
    if (blockIdx.x < 64){
        int i = blockIdx.x*1024 + t;
        int o = g_off_n[i] + g_aux[blockIdx.x];
        g_off_n[i] = o; g_cur_n[i] = o;
        int c = g_cnt_n[i];
        g_dinv2[i] = c > 0 ? 1.f/(float)c : 0.f;
        if (i == 0) g_off_n[NN] = EN;
    } else {
        int b2 = blockIdx.x - 64;
        int i = b2*1024 + t;
        if (i < RTT){
            int o = g_off_t[i] + g_aux[64 + b2];
            g_off_t[i] = o; g_cur_t[i] = o;
        }
        if (i == 0) g_off_t[RTT] = EN;
    }
}

// ---------------- per-relation attention scalars (layer 0) ----------------
__device__ __forceinline__ void relscal_body(int b2, const float* __restrict__ Wa,
        const float* __restrict__ Wb, const float* __restrict__ ba, const float* __restrict__ bb){
    int w = b2*8 + (threadIdx.x >> 5);
    int lane = threadIdx.x & 31;
    if (w >= RTT) return;
    float2 v = *(const float2*)(g_rel + (size_t)w*HH + 2*lane);
    float a0 = actf(v.x), a1 = actf(v.y);
    float2 wa1 = *(const float2*)(Wa + 2*lane);
    float2 wa2 = *(const float2*)(Wa + 64 + 2*lane);
    float2 wb1 = *(const float2*)(Wb + 2*lane);
    float2 wb2 = *(const float2*)(Wb + 64 + 2*lane);
    float sar = a0*wa1.x + a1*wa1.y;
    float saq = a0*wa2.x + a1*wa2.y;
    float sbr = v.x*wb1.x + v.y*wb1.y;
    float sbq = v.x*wb2.x + v.y*wb2.y;
    #pragma unroll
    for (int o=16;o;o>>=1){
        sar += __shfl_xor_sync(0xffffffffu,sar,o);
        saq += __shfl_xor_sync(0xffffffffu,saq,o);
        sbr += __shfl_xor_sync(0xffffffffu,sbr,o);
        sbq += __shfl_xor_sync(0xffffffffu,sbq,o);
    }
    if (lane == 0){ g_Ar[w]=sar+ba[0]; g_Aq[w]=saq; g_Br[w]=sbr+bb[0]; g_Bq[w]=sbq; }
}

// scatter | layer-0 relscal | zero cnt for next call
__global__ void k_scatter(const int* __restrict__ col, const int* __restrict__ row,
                          const int* __restrict__ et, const int* __restrict__ eq,
                          const float* __restrict__ Wa0, const float* __restrict__ Wb0,
                          const float* __restrict__ ba0, const float* __restrict__ bb0){
    int b = blockIdx.x;
    if (b < 1024){
        int e = b*blockDim.x + threadIdx.x;
        int c = col[e], r = row[e], t = et[e], q = eq[e];
        int p  = atomicAdd(&g_cur_n[r], 1);
        g_recN[p] = make_int4(c, t, q, 0);
        int p2 = atomicAdd(&g_cur_t[t], 1);
        g_recT[p2] = make_int4(c, r, q, 0);
    } else if (b < 2024){
        relscal_body(b - 1024, Wa0, Wb0, ba0, bb0);
    } else if (b < 2280){
        g_cnt_n[(b-2024)*256 + threadIdx.x] = 0;
    } else {
        int i = (b-2280)*256 + threadIdx.x;
        if (i < RTT) g_cnt_t[i] = 0;
    }
}

// ---------------- core proj body: conflict-free smem; !DOLN -> fp16 outputs ----------------
template<int TWO, int DOLN, int DOSCAL>
__device__ __forceinline__ void proj_body(
        int blk, const float* __restrict__ in, int nchunk, size_t cstride,
        const float* __restrict__ W, int wstride, int co1, int co2,
        void* __restrict__ out1, void* __restrict__ out2,
        const float* __restrict__ bias, const float* __restrict__ resid,
        float* __restrict__ outB,
        const float* __restrict__ Wa2, const float* __restrict__ Wb2,
        const float* __restrict__ ba2, const float* __restrict__ bb2)
{
    __shared__ float In[64][68];
    __shared__ float Wt[TWO+1][32][66];
    const int t = threadIdx.x;
    const int op = t & 31, rg = t >> 5;
    const size_t rowbase = (size_t)blk * 64;

    ull A0[4], B0[4], A1[4], B1[4];
    {
        ull z = pk2(0.f, 0.f);
        #pragma unroll
        for (int j=0;j<4;j++){ A0[j]=z; B0[j]=z; A1[j]=z; B1[j]=z; }
    }

    for (int c = 0; c < nchunk; c++){
        #pragma unroll 1
        for (int h = 0; h < 2; h++){
            __syncthreads();
            if (h == 0){
                const float* inc = in + (size_t)c*cstride + rowbase*HH;
                for (int idx = t; idx < 1024; idx += 256){
                    int r = idx & 63, kq = idx >> 6;
                    float4 v = *(const float4*)(inc + (size_t)r*HH + 4*kq);
                    In[4*kq+0][r]=v.x; In[4*kq+1][r]=v.y;
                    In[4*kq+2][r]=v.z; In[4*kq+3][r]=v.w;
                }
            }
            {
                int cob = c*64 + h*32;
                for (int idx = t; idx < 2048; idx += 256){
                    int o = idx >> 5, k = idx & 31;
                    Wt[0][k][o] = W[o*wstride + co1 + cob + k];
                    if (TWO) Wt[TWO][k][o] = W[o*wstride + co2 + cob + k];
                }
            }
            __syncthreads();
            #pragma unroll 8
            for (int k = 0; k < 32; k++){
                ulonglong2 v01 = *(const ulonglong2*)&In[h*32+k][rg*8];
                ulonglong2 v23 = *(const ulonglong2*)&In[h*32+k][rg*8+4];
                float2 w0 = *(const float2*)&Wt[0][k][2*op];
                ull wa = pk2(w0.x, w0.x), wb = pk2(w0.y, w0.y);
                ffma2(A0[0], v01.x, wa); ffma2(A0[1], v01.y, wa);
                ffma2(A0[2], v23.x, wa); ffma2(A0[3], v23.y, wa);
                ffma2(B0[0], v01.x, wb); ffma2(B0[1], v01.y, wb);
                ffma2(B0[2], v23.x, wb); ffma2(B0[3], v23.y, wb);
                if (TWO){
                    float2 w1 = *(const float2*)&Wt[TWO][k][2*op];
                    ull wc = pk2(w1.x, w1.x), wd = pk2(w1.y, w1.y);
                    ffma2(A1[0], v01.x, wc); ffma2(A1[1], v01.y, wc);
                    ffma2(A1[2], v23.x, wc); ffma2(A1[3], v23.y, wc);
                    ffma2(B1[0], v01.x, wd); ffma2(B1[1], v01.y, wd);
                    ffma2(B1[2], v23.x, wd); ffma2(B1[3], v23.y, wd);
                }
            }
        }
    }

    if (!DOLN){
        __half2* o1h = (__half2*)out1;
        __half2* o2h = (__half2*)out2;
        #pragma unroll
        for (int j = 0; j < 4; j++){
            size_t r0 = rowbase + rg*8 + 2*j;
            float a0,a1,b0,b1;
            upk2(A0[j], a0, a1); upk2(B0[j], b0, b1);
            o1h[r0*32 + op]     = __float22half2_rn(make_float2(a0, b0));
            o1h[(r0+1)*32 + op] = __float22half2_rn(make_float2(a1, b1));
            if (TWO){
                upk2(A1[j], a0, a1); upk2(B1[j], b0, b1);
                o2h[r0*32 + op]     = __float22half2_rn(make_float2(a0, b0));
                o2h[(r0+1)*32 + op] = __float22half2_rn(make_float2(a1, b1));
            }
        }
    } else {
        float* o1f = (float*)out1;
        float2 bv = *(const float2*)(bias + 2*op);
        float2 wa1, wav2, wb1, wbv2;
        bool doscal = DOSCAL && (Wa2 != 0);
        if (DOSCAL && doscal){
            wa1  = *(const float2*)(Wa2 + 2*op);
            wav2 = *(const float2*)(Wa2 + 64 + 2*op);
            wb1  = *(const float2*)(Wb2 + 2*op);
            wbv2 = *(const float2*)(Wb2 + 64 + 2*op);
        }
        #pragma unroll
        for (int j = 0; j < 4; j++){
            size_t r0 = rowbase + rg*8 + 2*j;
            float a0,a1,b0,b1;
            upk2(A0[j], a0, a1); upk2(B0[j], b0, b1);
            float y00 = actf(a0 + bv.x), y01 = actf(b0 + bv.y);
            float y10 = actf(a1 + bv.x), y11 = actf(b1 + bv.y);
            if (resid){
                float2 rv0 = *(const float2*)(resid + r0*HH + 2*op);
                float2 rv1 = *(const float2*)(resid + (r0+1)*HH + 2*op);
                y00 += rv0.x; y01 += rv0.y; y10 += rv1.x; y11 += rv1.y;
            }
            float s0 = y00+y01, q0 = y00*y00+y01*y01;
            float s1 = y10+y11, q1 = y10*y10+y11*y11;
            #pragma unroll
            for (int o=16;o;o>>=1){
                s0 += __shfl_xor_sync(0xffffffffu,s0,o);
                q0 += __shfl_xor_sync(0xffffffffu,q0,o);
                s1 += __shfl_xor_sync(0xffffffffu,s1,o);
                q1 += __shfl_xor_sync(0xffffffffu,q1,o);
            }
            float m0 = s0*(1.f/64.f), m1 = s1*(1.f/64.f);
            float i0 = rsqrtf(q0*(1.f/64.f) - m0*m0 + 1e-5f);
            float i1 = rsqrtf(q1*(1.f/64.f) - m1*m1 + 1e-5f);
            float2 w0 = make_float2((y00-m0)*i0, (y01-m0)*i0);
            float2 w1 = make_float2((y10-m1)*i1, (y11-m1)*i1);
            *(float2*)(o1f + r0*HH + 2*op)     = w0;
            *(float2*)(o1f + (r0+1)*HH + 2*op) = w1;
            if (outB){
                *(float2*)(outB + r0*HH + 2*op)     = w0;
                *(float2*)(outB + (r0+1)*HH + 2*op) = w1;
            }
            if (DOSCAL && doscal){
                float pa0 = actf(w0.x)*wa1.x + actf(w0.y)*wa1.y;
                float pq0 = actf(w0.x)*wav2.x + actf(w0.y)*wav2.y;
                float pb0 = w0.x*wb1.x + w0.y*wb1.y;
                float pc0 = w0.x*wbv2.x + w0.y*wbv2.y;
                float pa1 = actf(w1.x)*wa1.x + actf(w1.y)*wa1.y;
                float pq1 = actf(w1.x)*wav2.x + actf(w1.y)*wav2.y;
                float pb1 = w1.x*wb1.x + w1.y*wb1.y;
                float pc1 = w1.x*wbv2.x + w1.y*wbv2.y;
                #pragma unroll
                for (int o=16;o;o>>=1){
                    pa0 += __shfl_xor_sync(0xffffffffu,pa0,o);
                    pq0 += __shfl_xor_sync(0xffffffffu,pq0,o);
                    pb0 += __shfl_xor_sync(0xffffffffu,pb0,o);
                    pc0 += __shfl_xor_sync(0xffffffffu,pc0,o);
                    pa1 += __shfl_xor_sync(0xffffffffu,pa1,o);
                    pq1 += __shfl_xor_sync(0xffffffffu,pq1,o);
                    pb1 += __shfl_xor_sync(0xffffffffu,pb1,o);
                    pc1 += __shfl_xor_sync(0xffffffffu,pc1,o);
                }
                if (op == 0){
                    g_Ar[r0]   = pa0 + ba2[0]; g_Aq[r0]   = pq0;
                    g_Br[r0]   = pb0 + bb2[0]; g_Bq[r0]   = pc0;
                    g_Ar[r0+1] = pa1 + ba2[0]; g_Aq[r0+1] = pq1;
                    g_Br[r0+1] = pb1 + bb2[0]; g_Bq[r0+1] = pc1;
                }
            }
        }
    }
}

// ---------------- attention segment sums ----------------
__device__ __forceinline__ void absum_body(int b2){
    if (b2 < 256){
        int n = b2*256 + threadIdx.x;
        int b = g_off_n[n], e = g_off_n[n+1];
        float s = 0.f;
        for (int j = b; j < e; j++){
            int4 rc = g_recN[j];
            float a = __expf(g_Ar[rc.y] + g_Aq[rc.z]);
            g_aes[j] = a; s += a;
        }
        g_asum[n] = s;
    } else {
        int w = (b2 - 256)*8 + (threadIdx.x >> 5);
        int lane = threadIdx.x & 31;
        if (w >= RTT) return;
        int b = g_off_t[w], e = g_off_t[w+1];
        float br = g_Br[w];
        float s = 0.f;
        for (int j = b + lane; j < e; j += 32){
            int4 rc = g_recT[j];
            float bv = __expf(br + g_Bq[rc.z]);
            g_bes[j] = bv; s += bv;
        }
        #pragma unroll
        for (int o=16;o;o>>=1) s += __shfl_xor_sync(0xffffffffu,s,o);
        if (lane == 0) g_bsum[w] = s;
    }
}

// ---------------- loop update: one warp per query ----------------
__device__ __forceinline__ void loop_warp(int q, const float* __restrict__ Wl,
                                          const float* __restrict__ bl){
    int lane = threadIdx.x & 31;
    int qrow = g_qrows[q];
    float2 lv = *(const float2*)(g_loop + q*HH + 2*lane);
    float s0 = bl[2*lane], s1 = bl[2*lane+1];
    const float* lrow = g_loop + q*HH;
    const float* rrow = g_rel + (size_t)qrow*HH;
    const float* w0p = Wl + (size_t)(2*lane)*128;
    const float* w1p = w0p + 128;
    #pragma unroll 8
    for (int k = 0; k < 64; k++){
        float c = lrow[k];
        s0 = fmaf(c, w0p[k], s0); s1 = fmaf(c, w1p[k], s1);
    }
    #pragma unroll 8
    for (int k = 0; k < 64; k++){
        float c = rrow[k];
        s0 = fmaf(c, w0p[64+k], s0); s1 = fmaf(c, w1p[64+k], s1);
    }
    float y0 = lv.x + actf(s0), y1 = lv.y + actf(s1);
    float ss = y0+y1, sq = y0*y0+y1*y1;
    #pragma unroll
    for (int o=16;o;o>>=1){
        ss += __shfl_xor_sync(0xffffffffu,ss,o);
        sq += __shfl_xor_sync(0xffffffffu,sq,o);
    }
    float m = ss*(1.f/64.f);
    float inv = rsqrtf(sq*(1.f/64.f) - m*m + 1e-5f);
    *(float2*)(g_loop + q*HH + 2*lane) = make_float2((y0-m)*inv, (y1-m)*inv);
}

// ---------------- stage kernels ----------------
// stage1: Pr+Pq (rel dual) | Pq2 (rel single, for ht2r) | Ph (node) | absum | loop(prev)
__global__ __launch_bounds__(256, 3) void k_stage1(const float* __restrict__ Wmsg,
        const float* __restrict__ Wht,
        const float* __restrict__ Wl_prev, const float* __restrict__ bl_prev){
    int b = blockIdx.x;
    if (b < 125)
        proj_body<1,0,0>(b, g_rel, 1, 0, Wmsg, 192, 64, 128, g_prh, g_pqh, 0, 0, 0, 0,0,0,0);
    else if (b < 250)
        proj_body<0,0,0>(b-125, g_rel, 1, 0, Wht, 192, 128, 0, g_pq2h, 0, 0, 0, 0, 0,0,0,0);
    else if (b < 1274)
        proj_body<0,0,0>(b-250, g_node, 1, 0, Wmsg, 192, 0, 0, g_projAh, 0, 0, 0, 0, 0,0,0,0);
    else if (b < 2530)
        absum_body(b-1274);
    else {
        if (threadIdx.x < 32) loop_warp(b-2530, Wl_prev, bl_prev);
    }
}

// stage4: Ph2+Pt2 (node dual)
__global__ __launch_bounds__(256, 3) void k_stage4(const float* __restrict__ Wht){
    proj_body<1,0,0>(blockIdx.x, g_node, 1, 0, Wht, 192, 0, 64, g_projAh, g_projBh, 0, 0, 0, 0,0,0,0);
}

// stage3: node = LN(act(nacc @ We^T + be))
__global__ __launch_bounds__(256, 3) void k_stage3(const float* __restrict__ We,
        const float* __restrict__ be){
    proj_body<0,1,0>(blockIdx.x, g_nacc, 1, 0, We, 64, 0, 0, g_node, 0, be, 0, 0, 0,0,0,0);
}

// stage6: rel = LN(act(racc @ Wr^T + br) + rel); finals[i] = rel; + next-layer relscal
__global__ __launch_bounds__(256, 3) void k_stage6(const float* __restrict__ Wr,
        const float* __restrict__ br, float* __restrict__ finals_i,
        const float* __restrict__ Wa2, const float* __restrict__ Wb2,
        const float* __restrict__ ba2, const float* __restrict__ bb2){
    proj_body<0,1,1>(blockIdx.x, g_racc, 1, 0, Wr, 64, 0, 0, g_rel, 0, br, g_rel, finals_i,
                     Wa2, Wb2, ba2, bb2);
}

// final: fin = LN(act(concat(finals) @ Wf^T + bf)) | loop(layer 2)
__global__ __launch_bounds__(256, 3) void k_final(const float* __restrict__ Wf,
        const float* __restrict__ bf, const float* __restrict__ Wl2,
        const float* __restrict__ bl2){
    int b = blockIdx.x;
    if (b < 125)
        proj_body<0,1,0>(b, g_finals, 3, (size_t)RTT*HH, Wf, 192, 0, 0, g_fin, 0, bf, 0, 0, 0,0,0,0);
    else {
        if (threadIdx.x < 32) loop_warp(b-125, Wl2, bl2);
    }
}

// ---------------- edge message aggregation: warp per node (CSR, fp16 gathers) ----------------
__global__ void k_msg_agg(const int* __restrict__ row, const float* __restrict__ bmsg){
    int w = (blockIdx.x*blockDim.x + threadIdx.x) >> 5;
    int lane = threadIdx.x & 31;
    if (w >= NN) return;
    int b = g_off_n[w], e = g_off_n[w+1];
    float denom = g_asum[row[w]] + 1e-10f;    // faithful a_sum[row[row_e]]
    float sc0 = g_dinv2[w] / denom;
    float2 bm = *(const float2*)(bmsg + 2*lane);
    const __half2* phA = (const __half2*)g_projAh;
    const __half2* phR = (const __half2*)g_prh;
    const __half2* phQ = (const __half2*)g_pqh;
    float ax = 0.f, ay = 0.f;
    for (int j = b; j < e; j++){
        int4 rc = g_recN[j];
        float coef = g_aes[j] * sc0 * g_dinv2[rc.x];
        float2 ph = __half22float2(phA[(size_t)rc.x*32 + lane]);
        float2 pr = __half22float2(phR[(size_t)rc.y*32 + lane]);
        float2 pq = __half22float2(phQ[(size_t)rc.z*32 + lane]);
        ax += coef*actf(ph.x + pr.x + pq.x + bm.x);
        ay += coef*actf(ph.y + pr.y + pq.y + bm.y);
    }
    *(float2*)(g_nacc + (size_t)w*HH + 2*lane) = make_float2(ax, ay);
}

// ---------------- ht2r aggregation: warp per relation type (CSR, fp16 gathers) ----------------
__global__ void k_ht2r_agg(const int* __restrict__ et, const float* __restrict__ bht){
    int w = (blockIdx.x*blockDim.x + threadIdx.x) >> 5;
    int lane = threadIdx.x & 31;
    if (w >= RTT) return;
    int b = g_off_t[w], e = g_off_t[w+1];
    float inv_denom = 1.f / (g_bsum[et[w]] + 1e-10f);  // faithful b_sum[et[et_e]]
    float2 bm = *(const float2*)(bht + 2*lane);
    const __half2* phA = (const __half2*)g_projAh;
    const __half2* phB = (const __half2*)g_projBh;
    const __half2* phQ = (const __half2*)g_pq2h;
    float ax = 0.f, ay = 0.f;
    for (int j = b; j < e; j++){
        int4 rc = g_recT[j];
        float coef = g_bes[j] * inv_denom;
        float2 ph = __half22float2(phA[(size_t)rc.x*32 + lane]);
        float2 pt = __half22float2(phB[(size_t)rc.y*32 + lane]);
        float2 pq = __half22float2(phQ[(size_t)rc.z*32 + lane]);
        ax += coef*actf(ph.x + pt.x + pq.x + bm.x);
        ay += coef*actf(ph.y + pt.y + pq.y + bm.y);
    }
    *(float2*)(g_racc + (size_t)w*HH + 2*lane) = make_float2(ax, ay);
}

// ---------------- output means | zero rel for next call ----------------
__global__ void k_mean(float* __restrict__ out){
    int b = blockIdx.x;
    if (b < 402){
        int idx = b*256 + threadIdx.x;
        if (idx >= 8*201*64) return;
        int h = idx & 63;
        int rb = idx >> 6;
        int r = rb % 201;
        int bq = rb / 201;
        float s = 0.f;
        if (r < 200){
            #pragma unroll
            for (int s5=0;s5<5;s5++) s += g_fin[(bq*1000 + s5*200 + r)*HH + h];
        } else {
            #pragma unroll
            for (int s5=0;s5<5;s5++) s += g_loop[(bq*5 + s5)*HH + h];
        }
        out[idx] = s * 0.2f;
    } else {
        g_rel[(b-402)*256 + threadIdx.x] = 0.f;   // RTT*HH = 512000 = 2000 blocks
    }
}

// ---------------- host ----------------
struct Ptrs {
    const int *ei,*et,*eq,*hp,*tp,*qr,*lab;
    const float *pos,*srel,*lemb,*Wmsg,*bmsg,*Wht,*bht,*Wa,*ba,*Wb,*bb,*Wl,*bl,*We,*be,*Wr,*br,*Wf,*bf;
};

static void resolve(void* const* d, const int* sz, int n, Ptrs& p){
    int gi, wi;
    if (sz[0] == 2*EN){
        gi = 0;
        wi = (n > 10 && sz[7] == 1 && sz[8] == 1 && sz[9] == 1) ? 10 : 7;
    } else {
        wi = 0; gi = 19;
    }
    p.ei  = (const int*)d[gi+0]; p.et = (const int*)d[gi+1]; p.eq = (const int*)d[gi+2];
    p.hp  = (const int*)d[gi+3]; p.tp = (const int*)d[gi+4]; p.qr = (const int*)d[gi+5];
    p.lab = (const int*)d[gi+6];
    p.pos  = (const float*)d[wi+0];  p.srel = (const float*)d[wi+1];  p.lemb = (const float*)d[wi+2];
    p.Wmsg = (const float*)d[wi+3];  p.bmsg = (const float*)d[wi+4];
    p.Wht  = (const float*)d[wi+5];  p.bht  = (const float*)d[wi+6];
    p.Wa   = (const float*)d[wi+7];  p.ba   = (const float*)d[wi+8];
    p.Wb   = (const float*)d[wi+9];  p.bb   = (const float*)d[wi+10];
    p.Wl   = (const float*)d[wi+11]; p.bl   = (const float*)d[wi+12];
    p.We   = (const float*)d[wi+13]; p.be   = (const float*)d[wi+14];
    p.Wr   = (const float*)d[wi+15]; p.br   = (const float*)d[wi+16];
    p.Wf   = (const float*)d[wi+17]; p.bf   = (const float*)d[wi+18];
}

extern "C" void kernel_launch(void* const* d_in, const int* in_sizes, int n_in,
                              void* d_out, int out_size){
    Ptrs p; resolve(d_in, in_sizes, n_in, p);
    const int* col = p.ei;
    const int* row = p.ei + EN;

    float* s_finals;
    cudaGetSymbolAddress((void**)&s_finals, g_finals);

    // ---- init + CSR build (cnt/rel pre-zeroed by prior call's tails / module load) ----
    k_inithist<<<INIT_NODE_BLK + INIT_REL_BLK + INIT_HIST_BLK, 256>>>(
        p.lab, p.pos, p.hp, p.tp, p.qr, p.srel, p.lemb, row, p.et);
    k_scan1<<<72,1024>>>();
    k_scan2<<<2,64>>>();
    k_scan3<<<72,1024>>>();
    k_scatter<<<2312,256>>>(col, row, p.et, p.eq, p.Wa, p.Wb, p.ba, p.bb);

    for (int i = 0; i < 3; i++){
        const float* Wmsg = p.Wmsg + i*HH*192;
        const float* bmsg = p.bmsg + i*HH;
        const float* Wht  = p.Wht  + i*HH*192;
        const float* bht  = p.bht  + i*HH;
        const float* Wa2 = (i < 2) ? (p.Wa + (i+1)*128) : (const float*)0;
        const float* Wb2 = (i < 2) ? (p.Wb + (i+1)*128) : (const float*)0;
        const float* ba2 = (i < 2) ? (p.ba + (i+1)) : (const float*)0;
        const float* bb2 = (i < 2) ? (p.bb + (i+1)) : (const float*)0;

        int s1_blocks = (i == 0) ? 2530 : 2570;   // loop(prev) rides along for i>=1
        const float* Wlp = (i >= 1) ? (p.Wl + (i-1)*HH*128) : p.Wl;
        const float* blp = (i >= 1) ? (p.bl + (i-1)*HH) : p.bl;

        k_stage1<<<s1_blocks,256>>>(Wmsg, Wht, Wlp, blp);
        k_msg_agg<<<NN*32/256,256>>>(row, bmsg);
        k_stage3<<<1024,256>>>(p.We + i*HH*HH, p.be + i*HH);
        k_stage4<<<1024,256>>>(Wht);
        k_ht2r_agg<<<RTT*32/256,256>>>(p.et, bht);
        k_stage6<<<125,256>>>(p.Wr + i*HH*HH, p.br + i*HH, s_finals + i*RTT*HH,
                              Wa2, Wb2, ba2, bb2);
    }

    k_final<<<165,256>>>(p.Wf, p.bf, p.Wl + 2*HH*128, p.bl + 2*HH);
    k_mean<<<2402,256>>>((float*)d_out);
}